// round 14
// baseline (speedup 1.0000x reference)
#include <cuda_runtime.h>
#include <cuda_bf16.h>
#include <cstdint>
#include <math.h>

#define B_ 16
#define N_ 1024
#define D_ 256
#define H_ 8
#define DK_ 32
#define NUM_REL_ 3969   // (2*32-1)^2

// Scratch (allocation-free rule: __device__ globals). All interchange in
// pre-split bf16 hi/lo pairs (3-product fp32 emulation).
__device__ __nv_bfloat16 g_xhi[B_*N_*D_], g_xlo[B_*N_*D_];
__device__ __nv_bfloat16 g_whi[4*D_*D_], g_wlo[4*D_*D_];   // Wq|Wk|Wv|Wo
__device__ __nv_bfloat16 g_qhi[B_*H_*N_*DK_], g_qlo[B_*H_*N_*DK_];
__device__ __nv_bfloat16 g_khi[B_*H_*N_*DK_], g_klo[B_*H_*N_*DK_];
__device__ __nv_bfloat16 g_vhi[B_*H_*N_*DK_], g_vlo[B_*H_*N_*DK_];
__device__ __nv_bfloat16 g_ahi[B_*N_*D_],    g_alo[B_*N_*D_];

// ============================================================================
// helpers
// ============================================================================
__device__ __forceinline__ uint32_t smem_u32(const void* p) {
    uint32_t a;
    asm("{ .reg .u64 t; cvta.to.shared.u64 t, %1; cvt.u32.u64 %0, t; }" : "=r"(a) : "l"(p));
    return a;
}
__device__ __forceinline__ void ldsm_x4(uint32_t* r, uint32_t addr) {
    asm volatile("ldmatrix.sync.aligned.m8n8.x4.shared.b16 {%0,%1,%2,%3}, [%4];"
        : "=r"(r[0]), "=r"(r[1]), "=r"(r[2]), "=r"(r[3]) : "r"(addr));
}
__device__ __forceinline__ void ldsm_x4t(uint32_t* r, uint32_t addr) {
    asm volatile("ldmatrix.sync.aligned.m8n8.x4.trans.shared.b16 {%0,%1,%2,%3}, [%4];"
        : "=r"(r[0]), "=r"(r[1]), "=r"(r[2]), "=r"(r[3]) : "r"(addr));
}
__device__ __forceinline__ void mma16816(float* c, const uint32_t* a, const uint32_t* b) {
    asm volatile("mma.sync.aligned.m16n8k16.row.col.f32.bf16.bf16.f32 "
        "{%0,%1,%2,%3}, {%4,%5,%6,%7}, {%8,%9}, {%0,%1,%2,%3};"
        : "+f"(c[0]), "+f"(c[1]), "+f"(c[2]), "+f"(c[3])
        : "r"(a[0]), "r"(a[1]), "r"(a[2]), "r"(a[3]), "r"(b[0]), "r"(b[1]));
}
__device__ __forceinline__ float ex2f(float x) {
    float y;
    asm("ex2.approx.f32 %0, %1;" : "=f"(y) : "f"(x));
    return y;
}
__device__ __forceinline__ void split2(float p0, float p1, uint32_t& hi, uint32_t& lo) {
    __nv_bfloat162 h2 = __floats2bfloat162_rn(p0, p1);
    uint32_t hp = *reinterpret_cast<uint32_t*>(&h2);
    float h0 = __uint_as_float(hp << 16);
    float h1 = __uint_as_float(hp & 0xFFFF0000u);
    __nv_bfloat162 l2 = __floats2bfloat162_rn(p0 - h0, p1 - h1);
    hi = hp;
    lo = *reinterpret_cast<uint32_t*>(&l2);
}
#define CP16(s, g) asm volatile("cp.async.cg.shared.global [%0], [%1], 16;" \
    :: "r"(s), "l"(g) : "memory")
#define CP_COMMIT() asm volatile("cp.async.commit_group;" ::: "memory")
#define CP_WAIT0()  asm volatile("cp.async.wait_group 0;" ::: "memory")
#define CP_WAIT1()  asm volatile("cp.async.wait_group 1;" ::: "memory")

#define RSTRIDE 80   // bytes per smem row (40 bf16; 32 used) — ldmatrix conflict-free

// ============================================================================
// convert: x -> g_xhi/g_xlo ; Wq|Wk|Wv|Wo -> g_whi/g_wlo  (proven)
// ============================================================================
__global__ __launch_bounds__(256) void convert_kernel(
    const float* __restrict__ x,
    const float* __restrict__ Wq, const float* __restrict__ Wk,
    const float* __restrict__ Wv, const float* __restrict__ Wo)
{
    const int bid = blockIdx.x;
    const int tid = threadIdx.x;
    if (bid < 4096) {
        int i = bid * 256 + tid;
        float4 v = reinterpret_cast<const float4*>(x)[i];
        uint32_t h01, l01, h23, l23;
        split2(v.x, v.y, h01, l01);
        split2(v.z, v.w, h23, l23);
        reinterpret_cast<uint2*>(g_xhi)[i] = make_uint2(h01, h23);
        reinterpret_cast<uint2*>(g_xlo)[i] = make_uint2(l01, l23);
    } else {
        int i = (bid - 4096) * 256 + tid;
        int elem = i * 4;
        int mat = elem >> 16;
        int off = elem & 65535;
        const float* src = (mat == 0) ? Wq : (mat == 1) ? Wk : (mat == 2) ? Wv : Wo;
        float4 v = *reinterpret_cast<const float4*>(src + off);
        uint32_t h01, l01, h23, l23;
        split2(v.x, v.y, h01, l01);
        split2(v.z, v.w, h23, l23);
        reinterpret_cast<uint2*>(g_whi)[i] = make_uint2(h01, h23);
        reinterpret_cast<uint2*>(g_wlo)[i] = make_uint2(l01, l23);
    }
}

// ============================================================================
// GEMM (R12-proven, best measured): 512 threads, 16 warps 4(m) x 4(n),
// warp tile 32m x 16n, 3-stage cp.async, 2 CTA/SM.
// Per stage: A_HI 0 | A_LO 10240 | B_HI 20480 | B_LO 25600; stage 30720.
// ============================================================================
#define GA_HI 0
#define GA_LO 10240
#define GB_HI 20480
#define GB_LO 25600
#define GSTAGE 30720
#define GEMM_SMEM 92160

__device__ __forceinline__ void gemm_stage(
    uint32_t dst, const __nv_bfloat16* Ahi, const __nv_bfloat16* Alo,
    const __nv_bfloat16* Bhi, const __nv_bfloat16* Blo,
    int m0, int j0, int kb, int tid)
{
    const int row = tid >> 2, pos = tid & 3;   // row 0..127
    {
        size_t g = (size_t)(m0 + row) * 256 + kb * 32 + pos * 8;
        uint32_t s = dst + row * RSTRIDE + pos * 16;
        CP16(s + GA_HI, (const void*)(Ahi + g));
        CP16(s + GA_LO, (const void*)(Alo + g));
    }
    if (tid < 256) {
        size_t g = (size_t)(j0 + row) * 256 + kb * 32 + pos * 8;
        uint32_t s = dst + row * RSTRIDE + pos * 16;
        CP16(s + GB_HI, (const void*)(Bhi + g));
        CP16(s + GB_LO, (const void*)(Blo + g));
    }
    CP_COMMIT();
}

__device__ __forceinline__ void gemm_kblock(
    float acc[2][2][4], uint32_t buf, int wr, int wc, int l)
{
    uint32_t bh[2][4], bl[2][4];
    #pragma unroll
    for (int nt = 0; nt < 2; nt++) {
        uint32_t a = buf + GB_HI + (wc * 16 + nt * 8 + (l & 7)) * RSTRIDE + (l >> 3) * 16;
        ldsm_x4(bh[nt], a);
        ldsm_x4(bl[nt], a + (GB_LO - GB_HI));
    }
    #pragma unroll
    for (int ks = 0; ks < 2; ks++) {
        uint32_t ah[2][4], al[2][4];
        #pragma unroll
        for (int mt = 0; mt < 2; mt++) {
            uint32_t a = buf + GA_HI + (wr * 32 + mt * 16 + (l & 15)) * RSTRIDE
                       + ks * 32 + (l >> 4) * 16;
            ldsm_x4(ah[mt], a);
            ldsm_x4(al[mt], a + (GA_LO - GA_HI));
        }
        #pragma unroll
        for (int mt = 0; mt < 2; mt++)
            #pragma unroll
            for (int nt = 0; nt < 2; nt++)
                mma16816(acc[mt][nt], ah[mt], bh[nt] + 2 * ks);
        #pragma unroll
        for (int mt = 0; mt < 2; mt++)
            #pragma unroll
            for (int nt = 0; nt < 2; nt++)
                mma16816(acc[mt][nt], ah[mt], bl[nt] + 2 * ks);
        #pragma unroll
        for (int mt = 0; mt < 2; mt++)
            #pragma unroll
            for (int nt = 0; nt < 2; nt++)
                mma16816(acc[mt][nt], al[mt], bh[nt] + 2 * ks);
    }
}

// ============================================================================
// QKV projection. grid = (128 m-blocks, 12 j-blocks), 512 threads. 3-stage.
// ============================================================================
__global__ __launch_bounds__(512, 2) void qkv_hmma(
    const float* __restrict__ bq, const float* __restrict__ bk,
    const float* __restrict__ bv)
{
    extern __shared__ __align__(16) char smem[];
    const uint32_t sb = smem_u32(smem);

    const int tid = threadIdx.x;
    const int w = tid >> 5, l = tid & 31;
    const int wr = w & 3, wc = w >> 2;

    const int m0  = blockIdx.x * 128;
    const int j0  = blockIdx.y * 64;
    const int mat = j0 >> 8;
    const int jj0 = j0 & 255;

    const __nv_bfloat16* Whi = g_whi + mat * 65536;
    const __nv_bfloat16* Wlo = g_wlo + mat * 65536;

    float acc[2][2][4];
    #pragma unroll
    for (int mt = 0; mt < 2; mt++)
        #pragma unroll
        for (int nt = 0; nt < 2; nt++)
            #pragma unroll
            for (int i = 0; i < 4; i++) acc[mt][nt][i] = 0.f;

    gemm_stage(sb,          g_xhi, g_xlo, Whi, Wlo, m0, jj0, 0, tid);
    gemm_stage(sb + GSTAGE, g_xhi, g_xlo, Whi, Wlo, m0, jj0, 1, tid);

    int cur = 0, nxt = 2;
    for (int kb = 0; kb < 8; kb++) {
        const uint32_t buf = sb + cur * GSTAGE;
        CP_WAIT1();
        __syncthreads();
        if (kb < 6)
            gemm_stage(sb + nxt * GSTAGE, g_xhi, g_xlo, Whi, Wlo,
                       m0, jj0, kb + 2, tid);
        gemm_kblock(acc, buf, wr, wc, l);
        cur = (cur == 2) ? 0 : cur + 1;
        nxt = (nxt == 2) ? 0 : nxt + 1;
    }

    const float* bias = (mat == 0) ? bq : (mat == 1) ? bk : bv;
    __nv_bfloat16* dhi = (mat == 0) ? g_qhi : (mat == 1) ? g_khi : g_vhi;
    __nv_bfloat16* dlo = (mat == 0) ? g_qlo : (mat == 1) ? g_klo : g_vlo;
    const float sc = (mat == 0) ? (0.17677669529663689f * 1.4426950408889634f) : 1.f;

    #pragma unroll
    for (int mt = 0; mt < 2; mt++) {
        int m1 = m0 + wr * 32 + mt * 16 + (l >> 2);
        int m2 = m1 + 8;
        #pragma unroll
        for (int nt = 0; nt < 2; nt++) {
            int jj = jj0 + wc * 16 + nt * 8 + 2 * (l & 3);
            float b0 = bias[jj], b1 = bias[jj + 1];
            int hh = jj >> 5, d = jj & 31;
            uint32_t hi, lo;
            float v0 = (acc[mt][nt][0] + b0) * sc;
            float v1 = (acc[mt][nt][1] + b1) * sc;
            split2(v0, v1, hi, lo);
            size_t o1 = ((size_t)((m1 >> 10) * H_ + hh) * N_ + (m1 & 1023)) * DK_ + d;
            *(uint32_t*)(dhi + o1) = hi;
            *(uint32_t*)(dlo + o1) = lo;
            v0 = (acc[mt][nt][2] + b0) * sc;
            v1 = (acc[mt][nt][3] + b1) * sc;
            split2(v0, v1, hi, lo);
            size_t o2 = ((size_t)((m2 >> 10) * H_ + hh) * N_ + (m2 & 1023)) * DK_ + d;
            *(uint32_t*)(dhi + o2) = hi;
            *(uint32_t*)(dlo + o2) = lo;
        }
    }
}

// ============================================================================
// HMMA attention (R10/R12-proven numerics) with:
//  - windowed bias row: only 35 rel-rows (2205 floats, 8.8KB) needed per qt
//  - dual-batch CTAs: grid (8 qt, 8 h, 8 z); each CTA does bb = 2z, 2z+1
//    sharing the bias row (same head) across both work units.
// 256 threads, 8 warps x 16 q rows, cp.async double-buffered K/V.
// ============================================================================
#define BROW_N  2205    // 35*63
#define SM_BROW 0
#define SM_KV0  8832    // 16B aligned, after 8820B brow
#define SM_KV1  49792
#define KV_KHI  0
#define KV_KLO  10240
#define KV_VHI  20480
#define KV_VLO  30720
#define ATTN_SMEM 90752

__global__ __launch_bounds__(256, 2) void attn_kernel(
    const float* __restrict__ bias_table)
{
    extern __shared__ char smem[];
    float* brow = (float*)(smem);
    const uint32_t sb = smem_u32(smem);

    const int tid = threadIdx.x;
    const int w   = tid >> 5;
    const int l   = tid & 31;

    const int qt = blockIdx.x;
    const int h  = blockIdx.y;

    // windowed bias row: entries idx in [252*qt, 252*qt + 2205)
    {
        const float* bsrc = bias_table + h * NUM_REL_ + qt * 252;
        for (int i = tid; i < BROW_N; i += 256)
            brow[i] = bsrc[i] * 1.4426950408889634f;
    }

    // per-thread bias index constants (window-relative: subtract 252*qt)
    const int qg1 = qt * 128 + w * 16 + (l >> 2);
    const int qg2 = qg1 + 8;
    const int A1 = (qg1 >> 5) * 63 + (qg1 & 31) + 1984 - qt * 252;
    const int A2 = (qg2 >> 5) * 63 + (qg2 & 31) + 1984 - qt * 252;
    const int lc = 2 * (l & 3);

    for (int it = 0; it < 2; it++) {
        const int bb = blockIdx.z * 2 + it;
        const size_t headbase = (size_t)((bb * H_ + h) * N_) * DK_;

        // ---- stage Q tile into KV0 (plain stores; safe: kb=7 reads KV1) ----
        {
            const uint4* qhi4 = (const uint4*)(g_qhi + headbase + (size_t)qt * 128 * DK_);
            const uint4* qlo4 = (const uint4*)(g_qlo + headbase + (size_t)qt * 128 * DK_);
            #pragma unroll
            for (int i = 0; i < 2; i++) {
                int idx = tid + i * 256;
                int off = (idx >> 2) * RSTRIDE + (idx & 3) * 16;
                *(uint4*)(smem + SM_KV0 + KV_KHI + off) = qhi4[idx];
                *(uint4*)(smem + SM_KV0 + KV_KLO + off) = qlo4[idx];
            }
        }
        __syncthreads();   // Q staged (covers brow on it=0)

        uint32_t qh[2][4], ql[2][4];
        {
            int row = w * 16 + ((l >> 3) & 1) * 8 + (l & 7);
            int colb = (l >> 4) * 16;
            #pragma unroll
            for (int ks = 0; ks < 2; ks++) {
                ldsm_x4(qh[ks], sb + SM_KV0 + KV_KHI + row * RSTRIDE + ks * 32 + colb);
                ldsm_x4(ql[ks], sb + SM_KV0 + KV_KLO + row * RSTRIDE + ks * 32 + colb);
            }
        }
        __syncthreads();   // all q-frag ldsm done before cp.async overwrites KV0

        float o[4][4];
        #pragma unroll
        for (int i = 0; i < 4; i++)
            #pragma unroll
            for (int j = 0; j < 4; j++) o[i][j] = 0.f;
        float ls0 = 0.f, ls1 = 0.f;

        const __nv_bfloat16* khi = g_khi + headbase;
        const __nv_bfloat16* klo = g_klo + headbase;
        const __nv_bfloat16* vhi = g_vhi + headbase;
        const __nv_bfloat16* vlo = g_vlo + headbase;

        auto stage_kv = [&](int kb, uint32_t dst) {
            #pragma unroll
            for (int i = 0; i < 2; i++) {
                int idx = tid + i * 256;
                uint32_t off = (idx >> 2) * RSTRIDE + (idx & 3) * 16;
                size_t ge = (size_t)(kb * 512 + idx) * 8;
                CP16(dst + KV_KHI + off, (const void*)(khi + ge));
                CP16(dst + KV_KLO + off, (const void*)(klo + ge));
                CP16(dst + KV_VHI + off, (const void*)(vhi + ge));
                CP16(dst + KV_VLO + off, (const void*)(vlo + ge));
            }
            CP_COMMIT();
        };

        stage_kv(0, sb + SM_KV0);

        for (int kb = 0; kb < 8; kb++) {
            const uint32_t base = sb + ((kb & 1) ? SM_KV1 : SM_KV0);
            const uint32_t a_khi = base + KV_KHI;
            const uint32_t a_klo = base + KV_KLO;
            const uint32_t a_vhi = base + KV_VHI;
            const uint32_t a_vlo = base + KV_VLO;

            CP_WAIT0();
            __syncthreads();
            if (kb < 7)
                stage_kv(kb + 1, sb + (((kb + 1) & 1) ? SM_KV1 : SM_KV0));

            #pragma unroll
            for (int hf = 0; hf < 2; hf++) {
                uint32_t ph[16], pl[16];

                #pragma unroll
                for (int ntl = 0; ntl < 8; ntl++) {
                    const int nt = hf * 8 + ntl;
                    uint32_t kaddr = (nt * 8 + (l & 7)) * RSTRIDE + (l >> 3) * 16;
                    uint32_t kh[4], kl[4];
                    ldsm_x4(kh, a_khi + kaddr);
                    ldsm_x4(kl, a_klo + kaddr);

                    const int kr  = kb * 4 + (nt >> 2);
                    const int kc0 = (nt & 3) * 8 + lc;
                    const int Bv  = kr * 63 + kc0;
                    float bv0 = brow[A1 - Bv];
                    float bv1 = brow[A1 - Bv - 1];
                    float bv2 = brow[A2 - Bv];
                    float bv3 = brow[A2 - Bv - 1];

                    float acc[4]  = {0.f, 0.f, 0.f, 0.f};
                    float acc2[4] = {0.f, 0.f, 0.f, 0.f};
                    mma16816(acc,  qh[0], kh + 0);
                    mma16816(acc2, qh[0], kl + 0);
                    mma16816(acc,  qh[1], kh + 2);
                    mma16816(acc2, qh[1], kl + 2);
                    mma16816(acc2, ql[0], kh + 0);
                    mma16816(acc2, ql[1], kh + 2);

                    float p0 = ex2f(acc[0] + acc2[0] + bv0);
                    float p1 = ex2f(acc[1] + acc2[1] + bv1);
                    float p2 = ex2f(acc[2] + acc2[2] + bv2);
                    float p3 = ex2f(acc[3] + acc2[3] + bv3);
                    ls0 += p0 + p1;
                    ls1 += p2 + p3;

                    split2(p0, p1, ph[2 * ntl],     pl[2 * ntl]);
                    split2(p2, p3, ph[2 * ntl + 1], pl[2 * ntl + 1]);
                }

                #pragma unroll
                for (int i = 0; i < 2; i++) {
                    uint32_t vh[4][4], vl[4][4];
                    #pragma unroll
                    for (int nt = 0; nt < 4; nt++) {
                        uint32_t vaddr = (hf * 64 + i * 32 + (l >> 3) * 8 + (l & 7)) * RSTRIDE
                                       + nt * 16;
                        ldsm_x4t(vh[nt], a_vhi + vaddr);
                        ldsm_x4t(vl[nt], a_vlo + vaddr);
                    }
                    #pragma unroll
                    for (int nt = 0; nt < 4; nt++) {
                        mma16816(o[nt], ph + 8 * i,     vh[nt] + 0);
                        mma16816(o[nt], ph + 8 * i + 4, vh[nt] + 2);
                    }
                    #pragma unroll
                    for (int nt = 0; nt < 4; nt++) {
                        mma16816(o[nt], ph + 8 * i,     vl[nt] + 0);
                        mma16816(o[nt], ph + 8 * i + 4, vl[nt] + 2);
                    }
                    #pragma unroll
                    for (int nt = 0; nt < 4; nt++) {
                        mma16816(o[nt], pl + 8 * i,     vh[nt] + 0);
                        mma16816(o[nt], pl + 8 * i + 4, vh[nt] + 2);
                    }
                }
            }
        }

        ls0 += __shfl_xor_sync(0xffffffffu, ls0, 1);
        ls0 += __shfl_xor_sync(0xffffffffu, ls0, 2);
        ls1 += __shfl_xor_sync(0xffffffffu, ls1, 1);
        ls1 += __shfl_xor_sync(0xffffffffu, ls1, 2);
        const float inv0 = 1.f / ls0;
        const float inv1 = 1.f / ls1;

        const int row0 = bb * N_ + qt * 128 + w * 16 + (l >> 2);
        #pragma unroll
        for (int nt = 0; nt < 4; nt++) {
            int col = nt * 8 + lc;
            size_t e0 = (size_t)row0 * D_ + h * DK_ + col;
            size_t e1 = e0 + 8 * D_;
            uint32_t hi, lo;
            split2(o[nt][0] * inv0, o[nt][1] * inv0, hi, lo);
            *(uint32_t*)(g_ahi + e0) = hi;
            *(uint32_t*)(g_alo + e0) = lo;
            split2(o[nt][2] * inv1, o[nt][3] * inv1, hi, lo);
            *(uint32_t*)(g_ahi + e1) = hi;
            *(uint32_t*)(g_alo + e1) = lo;
        }
    }
}

// ============================================================================
// Output projection. grid = (128, 4), 512 threads. 3-stage. (R12-proven)
// ============================================================================
__global__ __launch_bounds__(512, 2) void oproj_hmma(
    const float* __restrict__ bo, float* __restrict__ out)
{
    extern __shared__ __align__(16) char smem[];
    const uint32_t sb = smem_u32(smem);

    const int tid = threadIdx.x;
    const int w = tid >> 5, l = tid & 31;
    const int wr = w & 3, wc = w >> 2;

    const int m0 = blockIdx.x * 128;
    const int j0 = blockIdx.y * 64;

    const __nv_bfloat16* Whi = g_whi + 3 * 65536;
    const __nv_bfloat16* Wlo = g_wlo + 3 * 65536;

    float acc[2][2][4];
    #pragma unroll
    for (int mt = 0; mt < 2; mt++)
        #pragma unroll
        for (int nt = 0; nt < 2; nt++)
            #pragma unroll
            for (int i = 0; i < 4; i++) acc[mt][nt][i] = 0.f;

    gemm_stage(sb,          g_ahi, g_alo, Whi, Wlo, m0, j0, 0, tid);
    gemm_stage(sb + GSTAGE, g_ahi, g_alo, Whi, Wlo, m0, j0, 1, tid);

    int cur = 0, nxt = 2;
    for (int kb = 0; kb < 8; kb++) {
        const uint32_t buf = sb + cur * GSTAGE;
        CP_WAIT1();
        __syncthreads();
        if (kb < 6)
            gemm_stage(sb + nxt * GSTAGE, g_ahi, g_alo, Whi, Wlo,
                       m0, j0, kb + 2, tid);
        gemm_kblock(acc, buf, wr, wc, l);
        cur = (cur == 2) ? 0 : cur + 1;
        nxt = (nxt == 2) ? 0 : nxt + 1;
    }

    #pragma unroll
    for (int mt = 0; mt < 2; mt++) {
        int m1 = m0 + wr * 32 + mt * 16 + (l >> 2);
        #pragma unroll
        for (int nt = 0; nt < 2; nt++) {
            int col = j0 + wc * 16 + nt * 8 + 2 * (l & 3);
            float b0 = bo[col], b1 = bo[col + 1];
            *(float2*)(out + (size_t)m1 * 256 + col) =
                make_float2(acc[mt][nt][0] + b0, acc[mt][nt][1] + b1);
            *(float2*)(out + (size_t)(m1 + 8) * 256 + col) =
                make_float2(acc[mt][nt][2] + b0, acc[mt][nt][3] + b1);
        }
    }
}

// ============================================================================
// Launch — inputs: x, Wq, bq, Wk, bk, Wv, bv, Wo, bo, bias_table, rel_index
// ============================================================================
extern "C" void kernel_launch(void* const* d_in, const int* in_sizes, int n_in,
                              void* d_out, int out_size)
{
    const float* x          = (const float*)d_in[0];
    const float* Wq         = (const float*)d_in[1];
    const float* bq         = (const float*)d_in[2];
    const float* Wk         = (const float*)d_in[3];
    const float* bk         = (const float*)d_in[4];
    const float* Wv         = (const float*)d_in[5];
    const float* bv         = (const float*)d_in[6];
    const float* Wo         = (const float*)d_in[7];
    const float* bo         = (const float*)d_in[8];
    const float* bias_table = (const float*)d_in[9];
    float* out = (float*)d_out;

    cudaFuncSetAttribute(attn_kernel, cudaFuncAttributeMaxDynamicSharedMemorySize, ATTN_SMEM);
    cudaFuncSetAttribute(qkv_hmma,  cudaFuncAttributeMaxDynamicSharedMemorySize, GEMM_SMEM);
    cudaFuncSetAttribute(oproj_hmma, cudaFuncAttributeMaxDynamicSharedMemorySize, GEMM_SMEM);

    convert_kernel<<<4352, 256>>>(x, Wq, Wk, Wv, Wo);
    qkv_hmma<<<dim3(128, 12), 512, GEMM_SMEM>>>(bq, bk, bv);
    attn_kernel<<<dim3(8, 8, 8), 256, ATTN_SMEM>>>(bias_table);
    oproj_hmma<<<dim3(128, 4), 512, GEMM_SMEM>>>(bo, out);
}

// round 15
// speedup vs baseline: 1.0907x; 1.0907x over previous
#include <cuda_runtime.h>
#include <cuda_bf16.h>
#include <cstdint>
#include <math.h>

#define B_ 16
#define N_ 1024
#define D_ 256
#define H_ 8
#define DK_ 32
#define NUM_REL_ 3969   // (2*32-1)^2

// Scratch (allocation-free rule: __device__ globals). All interchange in
// pre-split bf16 hi/lo pairs (3-product fp32 emulation).
__device__ __nv_bfloat16 g_xhi[B_*N_*D_], g_xlo[B_*N_*D_];
__device__ __nv_bfloat16 g_whi[4*D_*D_], g_wlo[4*D_*D_];   // Wq|Wk|Wv|Wo
__device__ __nv_bfloat16 g_qhi[B_*H_*N_*DK_], g_qlo[B_*H_*N_*DK_];
__device__ __nv_bfloat16 g_khi[B_*H_*N_*DK_], g_klo[B_*H_*N_*DK_];
__device__ __nv_bfloat16 g_vhi[B_*H_*N_*DK_], g_vlo[B_*H_*N_*DK_];
__device__ __nv_bfloat16 g_ahi[B_*N_*D_],    g_alo[B_*N_*D_];

// ============================================================================
// helpers
// ============================================================================
__device__ __forceinline__ uint32_t smem_u32(const void* p) {
    uint32_t a;
    asm("{ .reg .u64 t; cvta.to.shared.u64 t, %1; cvt.u32.u64 %0, t; }" : "=r"(a) : "l"(p));
    return a;
}
__device__ __forceinline__ void ldsm_x4(uint32_t* r, uint32_t addr) {
    asm volatile("ldmatrix.sync.aligned.m8n8.x4.shared.b16 {%0,%1,%2,%3}, [%4];"
        : "=r"(r[0]), "=r"(r[1]), "=r"(r[2]), "=r"(r[3]) : "r"(addr));
}
__device__ __forceinline__ void ldsm_x4t(uint32_t* r, uint32_t addr) {
    asm volatile("ldmatrix.sync.aligned.m8n8.x4.trans.shared.b16 {%0,%1,%2,%3}, [%4];"
        : "=r"(r[0]), "=r"(r[1]), "=r"(r[2]), "=r"(r[3]) : "r"(addr));
}
__device__ __forceinline__ void mma16816(float* c, const uint32_t* a, const uint32_t* b) {
    asm volatile("mma.sync.aligned.m16n8k16.row.col.f32.bf16.bf16.f32 "
        "{%0,%1,%2,%3}, {%4,%5,%6,%7}, {%8,%9}, {%0,%1,%2,%3};"
        : "+f"(c[0]), "+f"(c[1]), "+f"(c[2]), "+f"(c[3])
        : "r"(a[0]), "r"(a[1]), "r"(a[2]), "r"(a[3]), "r"(b[0]), "r"(b[1]));
}
__device__ __forceinline__ float ex2f(float x) {
    float y;
    asm("ex2.approx.f32 %0, %1;" : "=f"(y) : "f"(x));
    return y;
}
__device__ __forceinline__ void split2(float p0, float p1, uint32_t& hi, uint32_t& lo) {
    __nv_bfloat162 h2 = __floats2bfloat162_rn(p0, p1);
    uint32_t hp = *reinterpret_cast<uint32_t*>(&h2);
    float h0 = __uint_as_float(hp << 16);
    float h1 = __uint_as_float(hp & 0xFFFF0000u);
    __nv_bfloat162 l2 = __floats2bfloat162_rn(p0 - h0, p1 - h1);
    hi = hp;
    lo = *reinterpret_cast<uint32_t*>(&l2);
}
#define CP16(s, g) asm volatile("cp.async.cg.shared.global [%0], [%1], 16;" \
    :: "r"(s), "l"(g) : "memory")
#define CP_COMMIT() asm volatile("cp.async.commit_group;" ::: "memory")
#define CP_WAIT0()  asm volatile("cp.async.wait_group 0;" ::: "memory")
#define CP_WAIT1()  asm volatile("cp.async.wait_group 1;" ::: "memory")

#define RSTRIDE 80   // bytes per smem row (40 bf16; 32 used) — ldmatrix conflict-free

// ============================================================================
// convert: x -> g_xhi/g_xlo ; Wq|Wk|Wv|Wo -> g_whi/g_wlo  (proven)
// ============================================================================
__global__ __launch_bounds__(256) void convert_kernel(
    const float* __restrict__ x,
    const float* __restrict__ Wq, const float* __restrict__ Wk,
    const float* __restrict__ Wv, const float* __restrict__ Wo)
{
    const int bid = blockIdx.x;
    const int tid = threadIdx.x;
    if (bid < 4096) {
        int i = bid * 256 + tid;
        float4 v = reinterpret_cast<const float4*>(x)[i];
        uint32_t h01, l01, h23, l23;
        split2(v.x, v.y, h01, l01);
        split2(v.z, v.w, h23, l23);
        reinterpret_cast<uint2*>(g_xhi)[i] = make_uint2(h01, h23);
        reinterpret_cast<uint2*>(g_xlo)[i] = make_uint2(l01, l23);
    } else {
        int i = (bid - 4096) * 256 + tid;
        int elem = i * 4;
        int mat = elem >> 16;
        int off = elem & 65535;
        const float* src = (mat == 0) ? Wq : (mat == 1) ? Wk : (mat == 2) ? Wv : Wo;
        float4 v = *reinterpret_cast<const float4*>(src + off);
        uint32_t h01, l01, h23, l23;
        split2(v.x, v.y, h01, l01);
        split2(v.z, v.w, h23, l23);
        reinterpret_cast<uint2*>(g_whi)[i] = make_uint2(h01, h23);
        reinterpret_cast<uint2*>(g_wlo)[i] = make_uint2(l01, l23);
    }
}

// ============================================================================
// GEMM (R12-proven, best measured): 512 threads, 16 warps 4(m) x 4(n),
// warp tile 32m x 16n, 3-stage cp.async, 2 CTA/SM.
// Per stage: A_HI 0 | A_LO 10240 | B_HI 20480 | B_LO 25600; stage 30720.
// ============================================================================
#define GA_HI 0
#define GA_LO 10240
#define GB_HI 20480
#define GB_LO 25600
#define GSTAGE 30720
#define GEMM_SMEM 92160

__device__ __forceinline__ void gemm_stage(
    uint32_t dst, const __nv_bfloat16* Ahi, const __nv_bfloat16* Alo,
    const __nv_bfloat16* Bhi, const __nv_bfloat16* Blo,
    int m0, int j0, int kb, int tid)
{
    const int row = tid >> 2, pos = tid & 3;   // row 0..127
    {
        size_t g = (size_t)(m0 + row) * 256 + kb * 32 + pos * 8;
        uint32_t s = dst + row * RSTRIDE + pos * 16;
        CP16(s + GA_HI, (const void*)(Ahi + g));
        CP16(s + GA_LO, (const void*)(Alo + g));
    }
    if (tid < 256) {
        size_t g = (size_t)(j0 + row) * 256 + kb * 32 + pos * 8;
        uint32_t s = dst + row * RSTRIDE + pos * 16;
        CP16(s + GB_HI, (const void*)(Bhi + g));
        CP16(s + GB_LO, (const void*)(Blo + g));
    }
    CP_COMMIT();
}

__device__ __forceinline__ void gemm_kblock(
    float acc[2][2][4], uint32_t buf, int wr, int wc, int l)
{
    uint32_t bh[2][4], bl[2][4];
    #pragma unroll
    for (int nt = 0; nt < 2; nt++) {
        uint32_t a = buf + GB_HI + (wc * 16 + nt * 8 + (l & 7)) * RSTRIDE + (l >> 3) * 16;
        ldsm_x4(bh[nt], a);
        ldsm_x4(bl[nt], a + (GB_LO - GB_HI));
    }
    #pragma unroll
    for (int ks = 0; ks < 2; ks++) {
        uint32_t ah[2][4], al[2][4];
        #pragma unroll
        for (int mt = 0; mt < 2; mt++) {
            uint32_t a = buf + GA_HI + (wr * 32 + mt * 16 + (l & 15)) * RSTRIDE
                       + ks * 32 + (l >> 4) * 16;
            ldsm_x4(ah[mt], a);
            ldsm_x4(al[mt], a + (GA_LO - GA_HI));
        }
        #pragma unroll
        for (int mt = 0; mt < 2; mt++)
            #pragma unroll
            for (int nt = 0; nt < 2; nt++)
                mma16816(acc[mt][nt], ah[mt], bh[nt] + 2 * ks);
        #pragma unroll
        for (int mt = 0; mt < 2; mt++)
            #pragma unroll
            for (int nt = 0; nt < 2; nt++)
                mma16816(acc[mt][nt], ah[mt], bl[nt] + 2 * ks);
        #pragma unroll
        for (int mt = 0; mt < 2; mt++)
            #pragma unroll
            for (int nt = 0; nt < 2; nt++)
                mma16816(acc[mt][nt], al[mt], bh[nt] + 2 * ks);
    }
}

// ============================================================================
// QKV projection. grid = (128 m-blocks, 12 j-blocks), 512 threads. 3-stage.
// ============================================================================
__global__ __launch_bounds__(512, 2) void qkv_hmma(
    const float* __restrict__ bq, const float* __restrict__ bk,
    const float* __restrict__ bv)
{
    extern __shared__ __align__(16) char smem[];
    const uint32_t sb = smem_u32(smem);

    const int tid = threadIdx.x;
    const int w = tid >> 5, l = tid & 31;
    const int wr = w & 3, wc = w >> 2;

    const int m0  = blockIdx.x * 128;
    const int j0  = blockIdx.y * 64;
    const int mat = j0 >> 8;
    const int jj0 = j0 & 255;

    const __nv_bfloat16* Whi = g_whi + mat * 65536;
    const __nv_bfloat16* Wlo = g_wlo + mat * 65536;

    float acc[2][2][4];
    #pragma unroll
    for (int mt = 0; mt < 2; mt++)
        #pragma unroll
        for (int nt = 0; nt < 2; nt++)
            #pragma unroll
            for (int i = 0; i < 4; i++) acc[mt][nt][i] = 0.f;

    gemm_stage(sb,          g_xhi, g_xlo, Whi, Wlo, m0, jj0, 0, tid);
    gemm_stage(sb + GSTAGE, g_xhi, g_xlo, Whi, Wlo, m0, jj0, 1, tid);

    int cur = 0, nxt = 2;
    for (int kb = 0; kb < 8; kb++) {
        const uint32_t buf = sb + cur * GSTAGE;
        CP_WAIT1();
        __syncthreads();
        if (kb < 6)
            gemm_stage(sb + nxt * GSTAGE, g_xhi, g_xlo, Whi, Wlo,
                       m0, jj0, kb + 2, tid);
        gemm_kblock(acc, buf, wr, wc, l);
        cur = (cur == 2) ? 0 : cur + 1;
        nxt = (nxt == 2) ? 0 : nxt + 1;
    }

    const float* bias = (mat == 0) ? bq : (mat == 1) ? bk : bv;
    __nv_bfloat16* dhi = (mat == 0) ? g_qhi : (mat == 1) ? g_khi : g_vhi;
    __nv_bfloat16* dlo = (mat == 0) ? g_qlo : (mat == 1) ? g_klo : g_vlo;
    const float sc = (mat == 0) ? (0.17677669529663689f * 1.4426950408889634f) : 1.f;

    #pragma unroll
    for (int mt = 0; mt < 2; mt++) {
        int m1 = m0 + wr * 32 + mt * 16 + (l >> 2);
        int m2 = m1 + 8;
        #pragma unroll
        for (int nt = 0; nt < 2; nt++) {
            int jj = jj0 + wc * 16 + nt * 8 + 2 * (l & 3);
            float b0 = bias[jj], b1 = bias[jj + 1];
            int hh = jj >> 5, d = jj & 31;
            uint32_t hi, lo;
            float v0 = (acc[mt][nt][0] + b0) * sc;
            float v1 = (acc[mt][nt][1] + b1) * sc;
            split2(v0, v1, hi, lo);
            size_t o1 = ((size_t)((m1 >> 10) * H_ + hh) * N_ + (m1 & 1023)) * DK_ + d;
            *(uint32_t*)(dhi + o1) = hi;
            *(uint32_t*)(dlo + o1) = lo;
            v0 = (acc[mt][nt][2] + b0) * sc;
            v1 = (acc[mt][nt][3] + b1) * sc;
            split2(v0, v1, hi, lo);
            size_t o2 = ((size_t)((m2 >> 10) * H_ + hh) * N_ + (m2 & 1023)) * DK_ + d;
            *(uint32_t*)(dhi + o2) = hi;
            *(uint32_t*)(dlo + o2) = lo;
        }
    }
}

// ============================================================================
// HMMA attention (R12-exact structure and numerics; grid (8,8,16)) with the
// ONE R14 component that was numerics-identical and positive-EV: windowed
// bias row (2205 floats = 8.8KB instead of 3969 = 15.9KB per CTA).
// 256 threads, 8 warps x 16 q rows, cp.async double-buffered K/V.
// ============================================================================
#define BROW_N  2205    // 35*63
#define SM_KV0  8832    // 16B aligned, after 8820B brow
#define SM_KV1  49792
#define KV_KHI  0
#define KV_KLO  10240
#define KV_VHI  20480
#define KV_VLO  30720
#define ATTN_SMEM 90752

__global__ __launch_bounds__(256, 2) void attn_kernel(
    const float* __restrict__ bias_table)
{
    extern __shared__ char smem[];
    float* brow = (float*)(smem);
    const uint32_t sb = smem_u32(smem);

    const int tid = threadIdx.x;
    const int w   = tid >> 5;
    const int l   = tid & 31;

    const int qt = blockIdx.x;
    const int h  = blockIdx.y;
    const int bb = blockIdx.z;

    // windowed bias row: entries idx in [252*qt, 252*qt + 2205)
    {
        const float* bsrc = bias_table + h * NUM_REL_ + qt * 252;
        for (int i = tid; i < BROW_N; i += 256)
            brow[i] = bsrc[i] * 1.4426950408889634f;
    }

    const size_t headbase = (size_t)((bb * H_ + h) * N_) * DK_;
    {
        const uint4* qhi4 = (const uint4*)(g_qhi + headbase + (size_t)qt * 128 * DK_);
        const uint4* qlo4 = (const uint4*)(g_qlo + headbase + (size_t)qt * 128 * DK_);
        #pragma unroll
        for (int i = 0; i < 2; i++) {
            int idx = tid + i * 256;
            int off = (idx >> 2) * RSTRIDE + (idx & 3) * 16;
            *(uint4*)(smem + SM_KV0 + KV_KHI + off) = qhi4[idx];
            *(uint4*)(smem + SM_KV0 + KV_KLO + off) = qlo4[idx];
        }
    }
    __syncthreads();

    uint32_t qh[2][4], ql[2][4];
    {
        int row = w * 16 + ((l >> 3) & 1) * 8 + (l & 7);
        int colb = (l >> 4) * 16;
        #pragma unroll
        for (int ks = 0; ks < 2; ks++) {
            ldsm_x4(qh[ks], sb + SM_KV0 + KV_KHI + row * RSTRIDE + ks * 32 + colb);
            ldsm_x4(ql[ks], sb + SM_KV0 + KV_KLO + row * RSTRIDE + ks * 32 + colb);
        }
    }
    __syncthreads();   // all ldsm done before cp.async overwrites stage0

    // per-thread bias index constants (window-relative: subtract 252*qt)
    const int qg1 = qt * 128 + w * 16 + (l >> 2);
    const int qg2 = qg1 + 8;
    const int A1 = (qg1 >> 5) * 63 + (qg1 & 31) + 1984 - qt * 252;
    const int A2 = (qg2 >> 5) * 63 + (qg2 & 31) + 1984 - qt * 252;
    const int lc = 2 * (l & 3);

    float o[4][4];
    #pragma unroll
    for (int i = 0; i < 4; i++)
        #pragma unroll
        for (int j = 0; j < 4; j++) o[i][j] = 0.f;
    float ls0 = 0.f, ls1 = 0.f;

    const __nv_bfloat16* khi = g_khi + headbase;
    const __nv_bfloat16* klo = g_klo + headbase;
    const __nv_bfloat16* vhi = g_vhi + headbase;
    const __nv_bfloat16* vlo = g_vlo + headbase;

    auto stage_kv = [&](int kb, uint32_t dst) {
        #pragma unroll
        for (int i = 0; i < 2; i++) {
            int idx = tid + i * 256;
            uint32_t off = (idx >> 2) * RSTRIDE + (idx & 3) * 16;
            size_t ge = (size_t)(kb * 512 + idx) * 8;
            CP16(dst + KV_KHI + off, (const void*)(khi + ge));
            CP16(dst + KV_KLO + off, (const void*)(klo + ge));
            CP16(dst + KV_VHI + off, (const void*)(vhi + ge));
            CP16(dst + KV_VLO + off, (const void*)(vlo + ge));
        }
        CP_COMMIT();
    };

    stage_kv(0, sb + SM_KV0);

    for (int kb = 0; kb < 8; kb++) {
        const uint32_t base = sb + ((kb & 1) ? SM_KV1 : SM_KV0);
        const uint32_t a_khi = base + KV_KHI;
        const uint32_t a_klo = base + KV_KLO;
        const uint32_t a_vhi = base + KV_VHI;
        const uint32_t a_vlo = base + KV_VLO;

        CP_WAIT0();
        __syncthreads();
        if (kb < 7)
            stage_kv(kb + 1, sb + (((kb + 1) & 1) ? SM_KV1 : SM_KV0));

        #pragma unroll
        for (int hf = 0; hf < 2; hf++) {
            uint32_t ph[16], pl[16];

            #pragma unroll
            for (int ntl = 0; ntl < 8; ntl++) {
                const int nt = hf * 8 + ntl;
                uint32_t kaddr = (nt * 8 + (l & 7)) * RSTRIDE + (l >> 3) * 16;
                uint32_t kh[4], kl[4];
                ldsm_x4(kh, a_khi + kaddr);
                ldsm_x4(kl, a_klo + kaddr);

                const int kr  = kb * 4 + (nt >> 2);
                const int kc0 = (nt & 3) * 8 + lc;
                const int Bv  = kr * 63 + kc0;
                float bv0 = brow[A1 - Bv];
                float bv1 = brow[A1 - Bv - 1];
                float bv2 = brow[A2 - Bv];
                float bv3 = brow[A2 - Bv - 1];

                float acc[4]  = {0.f, 0.f, 0.f, 0.f};
                float acc2[4] = {0.f, 0.f, 0.f, 0.f};
                mma16816(acc,  qh[0], kh + 0);
                mma16816(acc2, qh[0], kl + 0);
                mma16816(acc,  qh[1], kh + 2);
                mma16816(acc2, qh[1], kl + 2);
                mma16816(acc2, ql[0], kh + 0);
                mma16816(acc2, ql[1], kh + 2);

                float p0 = ex2f(acc[0] + acc2[0] + bv0);
                float p1 = ex2f(acc[1] + acc2[1] + bv1);
                float p2 = ex2f(acc[2] + acc2[2] + bv2);
                float p3 = ex2f(acc[3] + acc2[3] + bv3);
                ls0 += p0 + p1;
                ls1 += p2 + p3;

                split2(p0, p1, ph[2 * ntl],     pl[2 * ntl]);
                split2(p2, p3, ph[2 * ntl + 1], pl[2 * ntl + 1]);
            }

            #pragma unroll
            for (int i = 0; i < 2; i++) {
                uint32_t vh[4][4], vl[4][4];
                #pragma unroll
                for (int nt = 0; nt < 4; nt++) {
                    uint32_t vaddr = (hf * 64 + i * 32 + (l >> 3) * 8 + (l & 7)) * RSTRIDE
                                   + nt * 16;
                    ldsm_x4t(vh[nt], a_vhi + vaddr);
                    ldsm_x4t(vl[nt], a_vlo + vaddr);
                }
                #pragma unroll
                for (int nt = 0; nt < 4; nt++) {
                    mma16816(o[nt], ph + 8 * i,     vh[nt] + 0);
                    mma16816(o[nt], ph + 8 * i + 4, vh[nt] + 2);
                }
                #pragma unroll
                for (int nt = 0; nt < 4; nt++) {
                    mma16816(o[nt], ph + 8 * i,     vl[nt] + 0);
                    mma16816(o[nt], ph + 8 * i + 4, vl[nt] + 2);
                }
                #pragma unroll
                for (int nt = 0; nt < 4; nt++) {
                    mma16816(o[nt], pl + 8 * i,     vh[nt] + 0);
                    mma16816(o[nt], pl + 8 * i + 4, vh[nt] + 2);
                }
            }
        }
    }

    ls0 += __shfl_xor_sync(0xffffffffu, ls0, 1);
    ls0 += __shfl_xor_sync(0xffffffffu, ls0, 2);
    ls1 += __shfl_xor_sync(0xffffffffu, ls1, 1);
    ls1 += __shfl_xor_sync(0xffffffffu, ls1, 2);
    const float inv0 = 1.f / ls0;
    const float inv1 = 1.f / ls1;

    const int row0 = bb * N_ + qt * 128 + w * 16 + (l >> 2);
    #pragma unroll
    for (int nt = 0; nt < 4; nt++) {
        int col = nt * 8 + lc;
        size_t e0 = (size_t)row0 * D_ + h * DK_ + col;
        size_t e1 = e0 + 8 * D_;
        uint32_t hi, lo;
        split2(o[nt][0] * inv0, o[nt][1] * inv0, hi, lo);
        *(uint32_t*)(g_ahi + e0) = hi;
        *(uint32_t*)(g_alo + e0) = lo;
        split2(o[nt][2] * inv1, o[nt][3] * inv1, hi, lo);
        *(uint32_t*)(g_ahi + e1) = hi;
        *(uint32_t*)(g_alo + e1) = lo;
    }
}

// ============================================================================
// Output projection. grid = (128, 4), 512 threads. 3-stage. (R12-proven)
// ============================================================================
__global__ __launch_bounds__(512, 2) void oproj_hmma(
    const float* __restrict__ bo, float* __restrict__ out)
{
    extern __shared__ __align__(16) char smem[];
    const uint32_t sb = smem_u32(smem);

    const int tid = threadIdx.x;
    const int w = tid >> 5, l = tid & 31;
    const int wr = w & 3, wc = w >> 2;

    const int m0 = blockIdx.x * 128;
    const int j0 = blockIdx.y * 64;

    const __nv_bfloat16* Whi = g_whi + 3 * 65536;
    const __nv_bfloat16* Wlo = g_wlo + 3 * 65536;

    float acc[2][2][4];
    #pragma unroll
    for (int mt = 0; mt < 2; mt++)
        #pragma unroll
        for (int nt = 0; nt < 2; nt++)
            #pragma unroll
            for (int i = 0; i < 4; i++) acc[mt][nt][i] = 0.f;

    gemm_stage(sb,          g_ahi, g_alo, Whi, Wlo, m0, j0, 0, tid);
    gemm_stage(sb + GSTAGE, g_ahi, g_alo, Whi, Wlo, m0, j0, 1, tid);

    int cur = 0, nxt = 2;
    for (int kb = 0; kb < 8; kb++) {
        const uint32_t buf = sb + cur * GSTAGE;
        CP_WAIT1();
        __syncthreads();
        if (kb < 6)
            gemm_stage(sb + nxt * GSTAGE, g_ahi, g_alo, Whi, Wlo,
                       m0, j0, kb + 2, tid);
        gemm_kblock(acc, buf, wr, wc, l);
        cur = (cur == 2) ? 0 : cur + 1;
        nxt = (nxt == 2) ? 0 : nxt + 1;
    }

    #pragma unroll
    for (int mt = 0; mt < 2; mt++) {
        int m1 = m0 + wr * 32 + mt * 16 + (l >> 2);
        #pragma unroll
        for (int nt = 0; nt < 2; nt++) {
            int col = j0 + wc * 16 + nt * 8 + 2 * (l & 3);
            float b0 = bo[col], b1 = bo[col + 1];
            *(float2*)(out + (size_t)m1 * 256 + col) =
                make_float2(acc[mt][nt][0] + b0, acc[mt][nt][1] + b1);
            *(float2*)(out + (size_t)(m1 + 8) * 256 + col) =
                make_float2(acc[mt][nt][2] + b0, acc[mt][nt][3] + b1);
        }
    }
}

// ============================================================================
// Launch — inputs: x, Wq, bq, Wk, bk, Wv, bv, Wo, bo, bias_table, rel_index
// ============================================================================
extern "C" void kernel_launch(void* const* d_in, const int* in_sizes, int n_in,
                              void* d_out, int out_size)
{
    const float* x          = (const float*)d_in[0];
    const float* Wq         = (const float*)d_in[1];
    const float* bq         = (const float*)d_in[2];
    const float* Wk         = (const float*)d_in[3];
    const float* bk         = (const float*)d_in[4];
    const float* Wv         = (const float*)d_in[5];
    const float* bv         = (const float*)d_in[6];
    const float* Wo         = (const float*)d_in[7];
    const float* bo         = (const float*)d_in[8];
    const float* bias_table = (const float*)d_in[9];
    float* out = (float*)d_out;

    cudaFuncSetAttribute(attn_kernel, cudaFuncAttributeMaxDynamicSharedMemorySize, ATTN_SMEM);
    cudaFuncSetAttribute(qkv_hmma,  cudaFuncAttributeMaxDynamicSharedMemorySize, GEMM_SMEM);
    cudaFuncSetAttribute(oproj_hmma, cudaFuncAttributeMaxDynamicSharedMemorySize, GEMM_SMEM);

    convert_kernel<<<4352, 256>>>(x, Wq, Wk, Wv, Wo);
    qkv_hmma<<<dim3(128, 12), 512, GEMM_SMEM>>>(bq, bk, bv);
    attn_kernel<<<dim3(8, 8, 16), 256, ATTN_SMEM>>>(bias_table);
    oproj_hmma<<<dim3(128, 4), 512, GEMM_SMEM>>>(bo, out);
}

// round 16
// speedup vs baseline: 1.0914x; 1.0006x over previous
#include <cuda_runtime.h>
#include <cuda_bf16.h>
#include <cstdint>
#include <math.h>

#define B_ 16
#define N_ 1024
#define D_ 256
#define H_ 8
#define DK_ 32
#define NUM_REL_ 3969   // (2*32-1)^2

// Scratch (allocation-free rule: __device__ globals). All interchange in
// pre-split bf16 hi/lo pairs (3-product fp32 emulation).
__device__ __nv_bfloat16 g_xhi[B_*N_*D_], g_xlo[B_*N_*D_];
__device__ __nv_bfloat16 g_whi[4*D_*D_], g_wlo[4*D_*D_];   // Wq|Wk|Wv|Wo
__device__ __nv_bfloat16 g_qhi[B_*H_*N_*DK_], g_qlo[B_*H_*N_*DK_];
__device__ __nv_bfloat16 g_khi[B_*H_*N_*DK_], g_klo[B_*H_*N_*DK_];
__device__ __nv_bfloat16 g_vhi[B_*H_*N_*DK_], g_vlo[B_*H_*N_*DK_];
__device__ __nv_bfloat16 g_ahi[B_*N_*D_],    g_alo[B_*N_*D_];

// ============================================================================
// helpers
// ============================================================================
__device__ __forceinline__ uint32_t smem_u32(const void* p) {
    uint32_t a;
    asm("{ .reg .u64 t; cvta.to.shared.u64 t, %1; cvt.u32.u64 %0, t; }" : "=r"(a) : "l"(p));
    return a;
}
__device__ __forceinline__ void ldsm_x4(uint32_t* r, uint32_t addr) {
    asm volatile("ldmatrix.sync.aligned.m8n8.x4.shared.b16 {%0,%1,%2,%3}, [%4];"
        : "=r"(r[0]), "=r"(r[1]), "=r"(r[2]), "=r"(r[3]) : "r"(addr));
}
__device__ __forceinline__ void ldsm_x4t(uint32_t* r, uint32_t addr) {
    asm volatile("ldmatrix.sync.aligned.m8n8.x4.trans.shared.b16 {%0,%1,%2,%3}, [%4];"
        : "=r"(r[0]), "=r"(r[1]), "=r"(r[2]), "=r"(r[3]) : "r"(addr));
}
__device__ __forceinline__ void mma16816(float* c, const uint32_t* a, const uint32_t* b) {
    asm volatile("mma.sync.aligned.m16n8k16.row.col.f32.bf16.bf16.f32 "
        "{%0,%1,%2,%3}, {%4,%5,%6,%7}, {%8,%9}, {%0,%1,%2,%3};"
        : "+f"(c[0]), "+f"(c[1]), "+f"(c[2]), "+f"(c[3])
        : "r"(a[0]), "r"(a[1]), "r"(a[2]), "r"(a[3]), "r"(b[0]), "r"(b[1]));
}
__device__ __forceinline__ float ex2f(float x) {
    float y;
    asm("ex2.approx.f32 %0, %1;" : "=f"(y) : "f"(x));
    return y;
}
__device__ __forceinline__ void split2(float p0, float p1, uint32_t& hi, uint32_t& lo) {
    __nv_bfloat162 h2 = __floats2bfloat162_rn(p0, p1);
    uint32_t hp = *reinterpret_cast<uint32_t*>(&h2);
    float h0 = __uint_as_float(hp << 16);
    float h1 = __uint_as_float(hp & 0xFFFF0000u);
    __nv_bfloat162 l2 = __floats2bfloat162_rn(p0 - h0, p1 - h1);
    hi = hp;
    lo = *reinterpret_cast<uint32_t*>(&l2);
}
#define CP16(s, g) asm volatile("cp.async.cg.shared.global [%0], [%1], 16;" \
    :: "r"(s), "l"(g) : "memory")
#define CP_COMMIT() asm volatile("cp.async.commit_group;" ::: "memory")
#define CP_WAIT0()  asm volatile("cp.async.wait_group 0;" ::: "memory")
#define CP_WAIT1()  asm volatile("cp.async.wait_group 1;" ::: "memory")

#define RSTRIDE 80   // bytes per smem row (40 bf16; 32 used) — ldmatrix conflict-free

// ============================================================================
// convert: x -> g_xhi/g_xlo ; Wq|Wk|Wv|Wo -> g_whi/g_wlo  (proven)
// ============================================================================
__global__ __launch_bounds__(256) void convert_kernel(
    const float* __restrict__ x,
    const float* __restrict__ Wq, const float* __restrict__ Wk,
    const float* __restrict__ Wv, const float* __restrict__ Wo)
{
    const int bid = blockIdx.x;
    const int tid = threadIdx.x;
    if (bid < 4096) {
        int i = bid * 256 + tid;
        float4 v = reinterpret_cast<const float4*>(x)[i];
        uint32_t h01, l01, h23, l23;
        split2(v.x, v.y, h01, l01);
        split2(v.z, v.w, h23, l23);
        reinterpret_cast<uint2*>(g_xhi)[i] = make_uint2(h01, h23);
        reinterpret_cast<uint2*>(g_xlo)[i] = make_uint2(l01, l23);
    } else {
        int i = (bid - 4096) * 256 + tid;
        int elem = i * 4;
        int mat = elem >> 16;
        int off = elem & 65535;
        const float* src = (mat == 0) ? Wq : (mat == 1) ? Wk : (mat == 2) ? Wv : Wo;
        float4 v = *reinterpret_cast<const float4*>(src + off);
        uint32_t h01, l01, h23, l23;
        split2(v.x, v.y, h01, l01);
        split2(v.z, v.w, h23, l23);
        reinterpret_cast<uint2*>(g_whi)[i] = make_uint2(h01, h23);
        reinterpret_cast<uint2*>(g_wlo)[i] = make_uint2(l01, l23);
    }
}

// ============================================================================
// GEMM (R12-proven, best measured): 512 threads, 16 warps 4(m) x 4(n),
// warp tile 32m x 16n, 3-stage cp.async, 2 CTA/SM.
// Per stage: A_HI 0 | A_LO 10240 | B_HI 20480 | B_LO 25600; stage 30720.
// ============================================================================
#define GA_HI 0
#define GA_LO 10240
#define GB_HI 20480
#define GB_LO 25600
#define GSTAGE 30720
#define GEMM_SMEM 92160

__device__ __forceinline__ void gemm_stage(
    uint32_t dst, const __nv_bfloat16* Ahi, const __nv_bfloat16* Alo,
    const __nv_bfloat16* Bhi, const __nv_bfloat16* Blo,
    int m0, int j0, int kb, int tid)
{
    const int row = tid >> 2, pos = tid & 3;   // row 0..127
    {
        size_t g = (size_t)(m0 + row) * 256 + kb * 32 + pos * 8;
        uint32_t s = dst + row * RSTRIDE + pos * 16;
        CP16(s + GA_HI, (const void*)(Ahi + g));
        CP16(s + GA_LO, (const void*)(Alo + g));
    }
    if (tid < 256) {
        size_t g = (size_t)(j0 + row) * 256 + kb * 32 + pos * 8;
        uint32_t s = dst + row * RSTRIDE + pos * 16;
        CP16(s + GB_HI, (const void*)(Bhi + g));
        CP16(s + GB_LO, (const void*)(Blo + g));
    }
    CP_COMMIT();
}

__device__ __forceinline__ void gemm_kblock(
    float acc[2][2][4], uint32_t buf, int wr, int wc, int l)
{
    uint32_t bh[2][4], bl[2][4];
    #pragma unroll
    for (int nt = 0; nt < 2; nt++) {
        uint32_t a = buf + GB_HI + (wc * 16 + nt * 8 + (l & 7)) * RSTRIDE + (l >> 3) * 16;
        ldsm_x4(bh[nt], a);
        ldsm_x4(bl[nt], a + (GB_LO - GB_HI));
    }
    #pragma unroll
    for (int ks = 0; ks < 2; ks++) {
        uint32_t ah[2][4], al[2][4];
        #pragma unroll
        for (int mt = 0; mt < 2; mt++) {
            uint32_t a = buf + GA_HI + (wr * 32 + mt * 16 + (l & 15)) * RSTRIDE
                       + ks * 32 + (l >> 4) * 16;
            ldsm_x4(ah[mt], a);
            ldsm_x4(al[mt], a + (GA_LO - GA_HI));
        }
        #pragma unroll
        for (int mt = 0; mt < 2; mt++)
            #pragma unroll
            for (int nt = 0; nt < 2; nt++)
                mma16816(acc[mt][nt], ah[mt], bh[nt] + 2 * ks);
        #pragma unroll
        for (int mt = 0; mt < 2; mt++)
            #pragma unroll
            for (int nt = 0; nt < 2; nt++)
                mma16816(acc[mt][nt], ah[mt], bl[nt] + 2 * ks);
        #pragma unroll
        for (int mt = 0; mt < 2; mt++)
            #pragma unroll
            for (int nt = 0; nt < 2; nt++)
                mma16816(acc[mt][nt], al[mt], bh[nt] + 2 * ks);
    }
}

// ============================================================================
// QKV projection. grid = (128 m-blocks, 12 j-blocks), 512 threads. 3-stage.
// ============================================================================
__global__ __launch_bounds__(512, 2) void qkv_hmma(
    const float* __restrict__ bq, const float* __restrict__ bk,
    const float* __restrict__ bv)
{
    extern __shared__ __align__(16) char smem[];
    const uint32_t sb = smem_u32(smem);

    const int tid = threadIdx.x;
    const int w = tid >> 5, l = tid & 31;
    const int wr = w & 3, wc = w >> 2;

    const int m0  = blockIdx.x * 128;
    const int j0  = blockIdx.y * 64;
    const int mat = j0 >> 8;
    const int jj0 = j0 & 255;

    const __nv_bfloat16* Whi = g_whi + mat * 65536;
    const __nv_bfloat16* Wlo = g_wlo + mat * 65536;

    float acc[2][2][4];
    #pragma unroll
    for (int mt = 0; mt < 2; mt++)
        #pragma unroll
        for (int nt = 0; nt < 2; nt++)
            #pragma unroll
            for (int i = 0; i < 4; i++) acc[mt][nt][i] = 0.f;

    gemm_stage(sb,          g_xhi, g_xlo, Whi, Wlo, m0, jj0, 0, tid);
    gemm_stage(sb + GSTAGE, g_xhi, g_xlo, Whi, Wlo, m0, jj0, 1, tid);

    int cur = 0, nxt = 2;
    for (int kb = 0; kb < 8; kb++) {
        const uint32_t buf = sb + cur * GSTAGE;
        CP_WAIT1();
        __syncthreads();
        if (kb < 6)
            gemm_stage(sb + nxt * GSTAGE, g_xhi, g_xlo, Whi, Wlo,
                       m0, jj0, kb + 2, tid);
        gemm_kblock(acc, buf, wr, wc, l);
        cur = (cur == 2) ? 0 : cur + 1;
        nxt = (nxt == 2) ? 0 : nxt + 1;
    }

    const float* bias = (mat == 0) ? bq : (mat == 1) ? bk : bv;
    __nv_bfloat16* dhi = (mat == 0) ? g_qhi : (mat == 1) ? g_khi : g_vhi;
    __nv_bfloat16* dlo = (mat == 0) ? g_qlo : (mat == 1) ? g_klo : g_vlo;
    const float sc = (mat == 0) ? (0.17677669529663689f * 1.4426950408889634f) : 1.f;

    #pragma unroll
    for (int mt = 0; mt < 2; mt++) {
        int m1 = m0 + wr * 32 + mt * 16 + (l >> 2);
        int m2 = m1 + 8;
        #pragma unroll
        for (int nt = 0; nt < 2; nt++) {
            int jj = jj0 + wc * 16 + nt * 8 + 2 * (l & 3);
            float b0 = bias[jj], b1 = bias[jj + 1];
            int hh = jj >> 5, d = jj & 31;
            uint32_t hi, lo;
            float v0 = (acc[mt][nt][0] + b0) * sc;
            float v1 = (acc[mt][nt][1] + b1) * sc;
            split2(v0, v1, hi, lo);
            size_t o1 = ((size_t)((m1 >> 10) * H_ + hh) * N_ + (m1 & 1023)) * DK_ + d;
            *(uint32_t*)(dhi + o1) = hi;
            *(uint32_t*)(dlo + o1) = lo;
            v0 = (acc[mt][nt][2] + b0) * sc;
            v1 = (acc[mt][nt][3] + b1) * sc;
            split2(v0, v1, hi, lo);
            size_t o2 = ((size_t)((m2 >> 10) * H_ + hh) * N_ + (m2 & 1023)) * DK_ + d;
            *(uint32_t*)(dhi + o2) = hi;
            *(uint32_t*)(dlo + o2) = lo;
        }
    }
}

// ============================================================================
// HMMA attention (R15 structure/numerics) with Q staged in slot KV1:
// the first overwrite of Q's slot is stage_kv(1) at kb=0, which is already
// behind the mainloop's CP_WAIT0+__syncthreads — so the second startup
// barrier is removed and stage_kv(0) issues earlier (overlapping Q ldsm).
// Windowed bias row: 2205 floats (8.8KB). 256 threads, 8 warps x 16 q rows.
// ============================================================================
#define BROW_N  2205    // 35*63
#define SM_KV0  8832    // 16B aligned, after 8820B brow
#define SM_KV1  49792
#define KV_KHI  0
#define KV_KLO  10240
#define KV_VHI  20480
#define KV_VLO  30720
#define ATTN_SMEM 90752

__global__ __launch_bounds__(256, 2) void attn_kernel(
    const float* __restrict__ bias_table)
{
    extern __shared__ char smem[];
    float* brow = (float*)(smem);
    const uint32_t sb = smem_u32(smem);

    const int tid = threadIdx.x;
    const int w   = tid >> 5;
    const int l   = tid & 31;

    const int qt = blockIdx.x;
    const int h  = blockIdx.y;
    const int bb = blockIdx.z;

    // windowed bias row: entries idx in [252*qt, 252*qt + 2205)
    {
        const float* bsrc = bias_table + h * NUM_REL_ + qt * 252;
        for (int i = tid; i < BROW_N; i += 256)
            brow[i] = bsrc[i] * 1.4426950408889634f;
    }

    const size_t headbase = (size_t)((bb * H_ + h) * N_) * DK_;

    // ---- stage Q tile into slot KV1 (plain stores) ----
    {
        const uint4* qhi4 = (const uint4*)(g_qhi + headbase + (size_t)qt * 128 * DK_);
        const uint4* qlo4 = (const uint4*)(g_qlo + headbase + (size_t)qt * 128 * DK_);
        #pragma unroll
        for (int i = 0; i < 2; i++) {
            int idx = tid + i * 256;
            int off = (idx >> 2) * RSTRIDE + (idx & 3) * 16;
            *(uint4*)(smem + SM_KV1 + KV_KHI + off) = qhi4[idx];
            *(uint4*)(smem + SM_KV1 + KV_KLO + off) = qlo4[idx];
        }
    }
    __syncthreads();   // Q staged (also covers brow)

    const __nv_bfloat16* khi = g_khi + headbase;
    const __nv_bfloat16* klo = g_klo + headbase;
    const __nv_bfloat16* vhi = g_vhi + headbase;
    const __nv_bfloat16* vlo = g_vlo + headbase;

    auto stage_kv = [&](int kb, uint32_t dst) {
        #pragma unroll
        for (int i = 0; i < 2; i++) {
            int idx = tid + i * 256;
            uint32_t off = (idx >> 2) * RSTRIDE + (idx & 3) * 16;
            size_t ge = (size_t)(kb * 512 + idx) * 8;
            CP16(dst + KV_KHI + off, (const void*)(khi + ge));
            CP16(dst + KV_KLO + off, (const void*)(klo + ge));
            CP16(dst + KV_VHI + off, (const void*)(vhi + ge));
            CP16(dst + KV_VLO + off, (const void*)(vlo + ge));
        }
        CP_COMMIT();
    };

    // kb=0 staging into KV0 can start immediately (Q lives in KV1)
    stage_kv(0, sb + SM_KV0);

    // Q fragments from KV1; per-thread ldsm complete before this thread's
    // kb=0 barrier, and stage_kv(1) (the first KV1 overwrite) comes after it.
    uint32_t qh[2][4], ql[2][4];
    {
        int row = w * 16 + ((l >> 3) & 1) * 8 + (l & 7);
        int colb = (l >> 4) * 16;
        #pragma unroll
        for (int ks = 0; ks < 2; ks++) {
            ldsm_x4(qh[ks], sb + SM_KV1 + KV_KHI + row * RSTRIDE + ks * 32 + colb);
            ldsm_x4(ql[ks], sb + SM_KV1 + KV_KLO + row * RSTRIDE + ks * 32 + colb);
        }
    }

    // per-thread bias index constants (window-relative: subtract 252*qt)
    const int qg1 = qt * 128 + w * 16 + (l >> 2);
    const int qg2 = qg1 + 8;
    const int A1 = (qg1 >> 5) * 63 + (qg1 & 31) + 1984 - qt * 252;
    const int A2 = (qg2 >> 5) * 63 + (qg2 & 31) + 1984 - qt * 252;
    const int lc = 2 * (l & 3);

    float o[4][4];
    #pragma unroll
    for (int i = 0; i < 4; i++)
        #pragma unroll
        for (int j = 0; j < 4; j++) o[i][j] = 0.f;
    float ls0 = 0.f, ls1 = 0.f;

    for (int kb = 0; kb < 8; kb++) {
        const uint32_t base = sb + ((kb & 1) ? SM_KV1 : SM_KV0);
        const uint32_t a_khi = base + KV_KHI;
        const uint32_t a_klo = base + KV_KLO;
        const uint32_t a_vhi = base + KV_VHI;
        const uint32_t a_vlo = base + KV_VLO;

        CP_WAIT0();
        __syncthreads();
        if (kb < 7)
            stage_kv(kb + 1, sb + (((kb + 1) & 1) ? SM_KV1 : SM_KV0));

        #pragma unroll
        for (int hf = 0; hf < 2; hf++) {
            uint32_t ph[16], pl[16];

            #pragma unroll
            for (int ntl = 0; ntl < 8; ntl++) {
                const int nt = hf * 8 + ntl;
                uint32_t kaddr = (nt * 8 + (l & 7)) * RSTRIDE + (l >> 3) * 16;
                uint32_t kh[4], kl[4];
                ldsm_x4(kh, a_khi + kaddr);
                ldsm_x4(kl, a_klo + kaddr);

                const int kr  = kb * 4 + (nt >> 2);
                const int kc0 = (nt & 3) * 8 + lc;
                const int Bv  = kr * 63 + kc0;
                float bv0 = brow[A1 - Bv];
                float bv1 = brow[A1 - Bv - 1];
                float bv2 = brow[A2 - Bv];
                float bv3 = brow[A2 - Bv - 1];

                float acc[4]  = {0.f, 0.f, 0.f, 0.f};
                float acc2[4] = {0.f, 0.f, 0.f, 0.f};
                mma16816(acc,  qh[0], kh + 0);
                mma16816(acc2, qh[0], kl + 0);
                mma16816(acc,  qh[1], kh + 2);
                mma16816(acc2, qh[1], kl + 2);
                mma16816(acc2, ql[0], kh + 0);
                mma16816(acc2, ql[1], kh + 2);

                float p0 = ex2f(acc[0] + acc2[0] + bv0);
                float p1 = ex2f(acc[1] + acc2[1] + bv1);
                float p2 = ex2f(acc[2] + acc2[2] + bv2);
                float p3 = ex2f(acc[3] + acc2[3] + bv3);
                ls0 += p0 + p1;
                ls1 += p2 + p3;

                split2(p0, p1, ph[2 * ntl],     pl[2 * ntl]);
                split2(p2, p3, ph[2 * ntl + 1], pl[2 * ntl + 1]);
            }

            #pragma unroll
            for (int i = 0; i < 2; i++) {
                uint32_t vh[4][4], vl[4][4];
                #pragma unroll
                for (int nt = 0; nt < 4; nt++) {
                    uint32_t vaddr = (hf * 64 + i * 32 + (l >> 3) * 8 + (l & 7)) * RSTRIDE
                                   + nt * 16;
                    ldsm_x4t(vh[nt], a_vhi + vaddr);
                    ldsm_x4t(vl[nt], a_vlo + vaddr);
                }
                #pragma unroll
                for (int nt = 0; nt < 4; nt++) {
                    mma16816(o[nt], ph + 8 * i,     vh[nt] + 0);
                    mma16816(o[nt], ph + 8 * i + 4, vh[nt] + 2);
                }
                #pragma unroll
                for (int nt = 0; nt < 4; nt++) {
                    mma16816(o[nt], ph + 8 * i,     vl[nt] + 0);
                    mma16816(o[nt], ph + 8 * i + 4, vl[nt] + 2);
                }
                #pragma unroll
                for (int nt = 0; nt < 4; nt++) {
                    mma16816(o[nt], pl + 8 * i,     vh[nt] + 0);
                    mma16816(o[nt], pl + 8 * i + 4, vh[nt] + 2);
                }
            }
        }
    }

    ls0 += __shfl_xor_sync(0xffffffffu, ls0, 1);
    ls0 += __shfl_xor_sync(0xffffffffu, ls0, 2);
    ls1 += __shfl_xor_sync(0xffffffffu, ls1, 1);
    ls1 += __shfl_xor_sync(0xffffffffu, ls1, 2);
    const float inv0 = 1.f / ls0;
    const float inv1 = 1.f / ls1;

    const int row0 = bb * N_ + qt * 128 + w * 16 + (l >> 2);
    #pragma unroll
    for (int nt = 0; nt < 4; nt++) {
        int col = nt * 8 + lc;
        size_t e0 = (size_t)row0 * D_ + h * DK_ + col;
        size_t e1 = e0 + 8 * D_;
        uint32_t hi, lo;
        split2(o[nt][0] * inv0, o[nt][1] * inv0, hi, lo);
        *(uint32_t*)(g_ahi + e0) = hi;
        *(uint32_t*)(g_alo + e0) = lo;
        split2(o[nt][2] * inv1, o[nt][3] * inv1, hi, lo);
        *(uint32_t*)(g_ahi + e1) = hi;
        *(uint32_t*)(g_alo + e1) = lo;
    }
}

// ============================================================================
// Output projection. grid = (128, 4), 512 threads. 3-stage. (R12-proven)
// ============================================================================
__global__ __launch_bounds__(512, 2) void oproj_hmma(
    const float* __restrict__ bo, float* __restrict__ out)
{
    extern __shared__ __align__(16) char smem[];
    const uint32_t sb = smem_u32(smem);

    const int tid = threadIdx.x;
    const int w = tid >> 5, l = tid & 31;
    const int wr = w & 3, wc = w >> 2;

    const int m0 = blockIdx.x * 128;
    const int j0 = blockIdx.y * 64;

    const __nv_bfloat16* Whi = g_whi + 3 * 65536;
    const __nv_bfloat16* Wlo = g_wlo + 3 * 65536;

    float acc[2][2][4];
    #pragma unroll
    for (int mt = 0; mt < 2; mt++)
        #pragma unroll
        for (int nt = 0; nt < 2; nt++)
            #pragma unroll
            for (int i = 0; i < 4; i++) acc[mt][nt][i] = 0.f;

    gemm_stage(sb,          g_ahi, g_alo, Whi, Wlo, m0, j0, 0, tid);
    gemm_stage(sb + GSTAGE, g_ahi, g_alo, Whi, Wlo, m0, j0, 1, tid);

    int cur = 0, nxt = 2;
    for (int kb = 0; kb < 8; kb++) {
        const uint32_t buf = sb + cur * GSTAGE;
        CP_WAIT1();
        __syncthreads();
        if (kb < 6)
            gemm_stage(sb + nxt * GSTAGE, g_ahi, g_alo, Whi, Wlo,
                       m0, j0, kb + 2, tid);
        gemm_kblock(acc, buf, wr, wc, l);
        cur = (cur == 2) ? 0 : cur + 1;
        nxt = (nxt == 2) ? 0 : nxt + 1;
    }

    #pragma unroll
    for (int mt = 0; mt < 2; mt++) {
        int m1 = m0 + wr * 32 + mt * 16 + (l >> 2);
        #pragma unroll
        for (int nt = 0; nt < 2; nt++) {
            int col = j0 + wc * 16 + nt * 8 + 2 * (l & 3);
            float b0 = bo[col], b1 = bo[col + 1];
            *(float2*)(out + (size_t)m1 * 256 + col) =
                make_float2(acc[mt][nt][0] + b0, acc[mt][nt][1] + b1);
            *(float2*)(out + (size_t)(m1 + 8) * 256 + col) =
                make_float2(acc[mt][nt][2] + b0, acc[mt][nt][3] + b1);
        }
    }
}

// ============================================================================
// Launch — inputs: x, Wq, bq, Wk, bk, Wv, bv, Wo, bo, bias_table, rel_index
// ============================================================================
extern "C" void kernel_launch(void* const* d_in, const int* in_sizes, int n_in,
                              void* d_out, int out_size)
{
    const float* x          = (const float*)d_in[0];
    const float* Wq         = (const float*)d_in[1];
    const float* bq         = (const float*)d_in[2];
    const float* Wk         = (const float*)d_in[3];
    const float* bk         = (const float*)d_in[4];
    const float* Wv         = (const float*)d_in[5];
    const float* bv         = (const float*)d_in[6];
    const float* Wo         = (const float*)d_in[7];
    const float* bo         = (const float*)d_in[8];
    const float* bias_table = (const float*)d_in[9];
    float* out = (float*)d_out;

    cudaFuncSetAttribute(attn_kernel, cudaFuncAttributeMaxDynamicSharedMemorySize, ATTN_SMEM);
    cudaFuncSetAttribute(qkv_hmma,  cudaFuncAttributeMaxDynamicSharedMemorySize, GEMM_SMEM);
    cudaFuncSetAttribute(oproj_hmma, cudaFuncAttributeMaxDynamicSharedMemorySize, GEMM_SMEM);

    convert_kernel<<<4352, 256>>>(x, Wq, Wk, Wv, Wo);
    qkv_hmma<<<dim3(128, 12), 512, GEMM_SMEM>>>(bq, bk, bv);
    attn_kernel<<<dim3(8, 8, 16), 256, ATTN_SMEM>>>(bias_table);
    oproj_hmma<<<dim3(128, 4), 512, GEMM_SMEM>>>(bo, out);
}

// round 17
// speedup vs baseline: 1.1068x; 1.0141x over previous
#include <cuda_runtime.h>
#include <cuda_bf16.h>
#include <cstdint>
#include <math.h>

#define B_ 16
#define N_ 1024
#define D_ 256
#define H_ 8
#define DK_ 32
#define NUM_REL_ 3969   // (2*32-1)^2

// Scratch (allocation-free rule: __device__ globals). All interchange in
// pre-split bf16 hi/lo pairs (3-product fp32 emulation).
__device__ __nv_bfloat16 g_xhi[B_*N_*D_], g_xlo[B_*N_*D_];
__device__ __nv_bfloat16 g_whi[4*D_*D_], g_wlo[4*D_*D_];   // Wq|Wk|Wv|Wo
__device__ __nv_bfloat16 g_qhi[B_*H_*N_*DK_], g_qlo[B_*H_*N_*DK_];
__device__ __nv_bfloat16 g_khi[B_*H_*N_*DK_], g_klo[B_*H_*N_*DK_];
__device__ __nv_bfloat16 g_vhi[B_*H_*N_*DK_], g_vlo[B_*H_*N_*DK_];
__device__ __nv_bfloat16 g_ahi[B_*N_*D_],    g_alo[B_*N_*D_];

// ============================================================================
// helpers
// ============================================================================
__device__ __forceinline__ uint32_t smem_u32(const void* p) {
    uint32_t a;
    asm("{ .reg .u64 t; cvta.to.shared.u64 t, %1; cvt.u32.u64 %0, t; }" : "=r"(a) : "l"(p));
    return a;
}
__device__ __forceinline__ void ldsm_x4(uint32_t* r, uint32_t addr) {
    asm volatile("ldmatrix.sync.aligned.m8n8.x4.shared.b16 {%0,%1,%2,%3}, [%4];"
        : "=r"(r[0]), "=r"(r[1]), "=r"(r[2]), "=r"(r[3]) : "r"(addr));
}
__device__ __forceinline__ void ldsm_x4t(uint32_t* r, uint32_t addr) {
    asm volatile("ldmatrix.sync.aligned.m8n8.x4.trans.shared.b16 {%0,%1,%2,%3}, [%4];"
        : "=r"(r[0]), "=r"(r[1]), "=r"(r[2]), "=r"(r[3]) : "r"(addr));
}
__device__ __forceinline__ void mma16816(float* c, const uint32_t* a, const uint32_t* b) {
    asm volatile("mma.sync.aligned.m16n8k16.row.col.f32.bf16.bf16.f32 "
        "{%0,%1,%2,%3}, {%4,%5,%6,%7}, {%8,%9}, {%0,%1,%2,%3};"
        : "+f"(c[0]), "+f"(c[1]), "+f"(c[2]), "+f"(c[3])
        : "r"(a[0]), "r"(a[1]), "r"(a[2]), "r"(a[3]), "r"(b[0]), "r"(b[1]));
}
__device__ __forceinline__ float ex2f(float x) {
    float y;
    asm("ex2.approx.f32 %0, %1;" : "=f"(y) : "f"(x));
    return y;
}
__device__ __forceinline__ void split2(float p0, float p1, uint32_t& hi, uint32_t& lo) {
    __nv_bfloat162 h2 = __floats2bfloat162_rn(p0, p1);
    uint32_t hp = *reinterpret_cast<uint32_t*>(&h2);
    float h0 = __uint_as_float(hp << 16);
    float h1 = __uint_as_float(hp & 0xFFFF0000u);
    __nv_bfloat162 l2 = __floats2bfloat162_rn(p0 - h0, p1 - h1);
    hi = hp;
    lo = *reinterpret_cast<uint32_t*>(&l2);
}
#define CP16(s, g) asm volatile("cp.async.cg.shared.global [%0], [%1], 16;" \
    :: "r"(s), "l"(g) : "memory")
#define CP_COMMIT() asm volatile("cp.async.commit_group;" ::: "memory")
#define CP_WAIT0()  asm volatile("cp.async.wait_group 0;" ::: "memory")
#define CP_WAIT1()  asm volatile("cp.async.wait_group 1;" ::: "memory")

#define RSTRIDE 80   // bytes per smem row (40 bf16; 32 used) — ldmatrix conflict-free

// ============================================================================
// convert: x -> g_xhi/g_xlo ; Wq|Wk|Wv|Wo -> g_whi/g_wlo  (proven)
// ============================================================================
__global__ __launch_bounds__(256) void convert_kernel(
    const float* __restrict__ x,
    const float* __restrict__ Wq, const float* __restrict__ Wk,
    const float* __restrict__ Wv, const float* __restrict__ Wo)
{
    const int bid = blockIdx.x;
    const int tid = threadIdx.x;
    if (bid < 4096) {
        int i = bid * 256 + tid;
        float4 v = reinterpret_cast<const float4*>(x)[i];
        uint32_t h01, l01, h23, l23;
        split2(v.x, v.y, h01, l01);
        split2(v.z, v.w, h23, l23);
        reinterpret_cast<uint2*>(g_xhi)[i] = make_uint2(h01, h23);
        reinterpret_cast<uint2*>(g_xlo)[i] = make_uint2(l01, l23);
    } else {
        int i = (bid - 4096) * 256 + tid;
        int elem = i * 4;
        int mat = elem >> 16;
        int off = elem & 65535;
        const float* src = (mat == 0) ? Wq : (mat == 1) ? Wk : (mat == 2) ? Wv : Wo;
        float4 v = *reinterpret_cast<const float4*>(src + off);
        uint32_t h01, l01, h23, l23;
        split2(v.x, v.y, h01, l01);
        split2(v.z, v.w, h23, l23);
        reinterpret_cast<uint2*>(g_whi)[i] = make_uint2(h01, h23);
        reinterpret_cast<uint2*>(g_wlo)[i] = make_uint2(l01, l23);
    }
}

// ============================================================================
// GEMM (R12/R16-proven): 512 threads, 16 warps 4(m) x 4(n), warp tile
// 32m x 16n, 3-stage cp.async, 2 CTA/SM. kb loop fully unrolled; final
// iteration uses wait_group 0 (closes the latent tail race where the last
// stage's group was the only outstanding one and wait_group 1 was a no-op).
// Per stage: A_HI 0 | A_LO 10240 | B_HI 20480 | B_LO 25600; stage 30720.
// ============================================================================
#define GA_HI 0
#define GA_LO 10240
#define GB_HI 20480
#define GB_LO 25600
#define GSTAGE 30720
#define GEMM_SMEM 92160

__device__ __forceinline__ void gemm_stage(
    uint32_t dst, const __nv_bfloat16* Ahi, const __nv_bfloat16* Alo,
    const __nv_bfloat16* Bhi, const __nv_bfloat16* Blo,
    int m0, int j0, int kb, int tid)
{
    const int row = tid >> 2, pos = tid & 3;   // row 0..127
    {
        size_t g = (size_t)(m0 + row) * 256 + kb * 32 + pos * 8;
        uint32_t s = dst + row * RSTRIDE + pos * 16;
        CP16(s + GA_HI, (const void*)(Ahi + g));
        CP16(s + GA_LO, (const void*)(Alo + g));
    }
    if (tid < 256) {
        size_t g = (size_t)(j0 + row) * 256 + kb * 32 + pos * 8;
        uint32_t s = dst + row * RSTRIDE + pos * 16;
        CP16(s + GB_HI, (const void*)(Bhi + g));
        CP16(s + GB_LO, (const void*)(Blo + g));
    }
    CP_COMMIT();
}

__device__ __forceinline__ void gemm_kblock(
    float acc[2][2][4], uint32_t buf, int wr, int wc, int l)
{
    uint32_t bh[2][4], bl[2][4];
    #pragma unroll
    for (int nt = 0; nt < 2; nt++) {
        uint32_t a = buf + GB_HI + (wc * 16 + nt * 8 + (l & 7)) * RSTRIDE + (l >> 3) * 16;
        ldsm_x4(bh[nt], a);
        ldsm_x4(bl[nt], a + (GB_LO - GB_HI));
    }
    #pragma unroll
    for (int ks = 0; ks < 2; ks++) {
        uint32_t ah[2][4], al[2][4];
        #pragma unroll
        for (int mt = 0; mt < 2; mt++) {
            uint32_t a = buf + GA_HI + (wr * 32 + mt * 16 + (l & 15)) * RSTRIDE
                       + ks * 32 + (l >> 4) * 16;
            ldsm_x4(ah[mt], a);
            ldsm_x4(al[mt], a + (GA_LO - GA_HI));
        }
        #pragma unroll
        for (int mt = 0; mt < 2; mt++)
            #pragma unroll
            for (int nt = 0; nt < 2; nt++)
                mma16816(acc[mt][nt], ah[mt], bh[nt] + 2 * ks);
        #pragma unroll
        for (int mt = 0; mt < 2; mt++)
            #pragma unroll
            for (int nt = 0; nt < 2; nt++)
                mma16816(acc[mt][nt], ah[mt], bl[nt] + 2 * ks);
        #pragma unroll
        for (int mt = 0; mt < 2; mt++)
            #pragma unroll
            for (int nt = 0; nt < 2; nt++)
                mma16816(acc[mt][nt], al[mt], bh[nt] + 2 * ks);
    }
}

// shared fully-unrolled 3-stage mainloop (compile-time kb; exact waits)
__device__ __forceinline__ void gemm_mainloop(
    float acc[2][2][4], uint32_t sb,
    const __nv_bfloat16* Ahi, const __nv_bfloat16* Alo,
    const __nv_bfloat16* Bhi, const __nv_bfloat16* Blo,
    int m0, int j0, int tid, int wr, int wc, int l)
{
    gemm_stage(sb,          Ahi, Alo, Bhi, Blo, m0, j0, 0, tid);
    gemm_stage(sb + GSTAGE, Ahi, Alo, Bhi, Blo, m0, j0, 1, tid);

    #pragma unroll
    for (int kb = 0; kb < 8; kb++) {
        const uint32_t buf = sb + (kb % 3) * GSTAGE;
        if (kb < 7) { CP_WAIT1(); } else { CP_WAIT0(); }   // last: full drain
        __syncthreads();
        if (kb < 6)
            gemm_stage(sb + ((kb + 2) % 3) * GSTAGE, Ahi, Alo, Bhi, Blo,
                       m0, j0, kb + 2, tid);
        gemm_kblock(acc, buf, wr, wc, l);
    }
}

// ============================================================================
// QKV projection. grid = (128 m-blocks, 12 j-blocks), 512 threads. 3-stage.
// ============================================================================
__global__ __launch_bounds__(512, 2) void qkv_hmma(
    const float* __restrict__ bq, const float* __restrict__ bk,
    const float* __restrict__ bv)
{
    extern __shared__ __align__(16) char smem[];
    const uint32_t sb = smem_u32(smem);

    const int tid = threadIdx.x;
    const int w = tid >> 5, l = tid & 31;
    const int wr = w & 3, wc = w >> 2;

    const int m0  = blockIdx.x * 128;
    const int j0  = blockIdx.y * 64;
    const int mat = j0 >> 8;
    const int jj0 = j0 & 255;

    const __nv_bfloat16* Whi = g_whi + mat * 65536;
    const __nv_bfloat16* Wlo = g_wlo + mat * 65536;

    float acc[2][2][4];
    #pragma unroll
    for (int mt = 0; mt < 2; mt++)
        #pragma unroll
        for (int nt = 0; nt < 2; nt++)
            #pragma unroll
            for (int i = 0; i < 4; i++) acc[mt][nt][i] = 0.f;

    gemm_mainloop(acc, sb, g_xhi, g_xlo, Whi, Wlo, m0, jj0, tid, wr, wc, l);

    const float* bias = (mat == 0) ? bq : (mat == 1) ? bk : bv;
    __nv_bfloat16* dhi = (mat == 0) ? g_qhi : (mat == 1) ? g_khi : g_vhi;
    __nv_bfloat16* dlo = (mat == 0) ? g_qlo : (mat == 1) ? g_klo : g_vlo;
    const float sc = (mat == 0) ? (0.17677669529663689f * 1.4426950408889634f) : 1.f;

    #pragma unroll
    for (int mt = 0; mt < 2; mt++) {
        int m1 = m0 + wr * 32 + mt * 16 + (l >> 2);
        int m2 = m1 + 8;
        #pragma unroll
        for (int nt = 0; nt < 2; nt++) {
            int jj = jj0 + wc * 16 + nt * 8 + 2 * (l & 3);
            float b0 = bias[jj], b1 = bias[jj + 1];
            int hh = jj >> 5, d = jj & 31;
            uint32_t hi, lo;
            float v0 = (acc[mt][nt][0] + b0) * sc;
            float v1 = (acc[mt][nt][1] + b1) * sc;
            split2(v0, v1, hi, lo);
            size_t o1 = ((size_t)((m1 >> 10) * H_ + hh) * N_ + (m1 & 1023)) * DK_ + d;
            *(uint32_t*)(dhi + o1) = hi;
            *(uint32_t*)(dlo + o1) = lo;
            v0 = (acc[mt][nt][2] + b0) * sc;
            v1 = (acc[mt][nt][3] + b1) * sc;
            split2(v0, v1, hi, lo);
            size_t o2 = ((size_t)((m2 >> 10) * H_ + hh) * N_ + (m2 & 1023)) * DK_ + d;
            *(uint32_t*)(dhi + o2) = hi;
            *(uint32_t*)(dlo + o2) = lo;
        }
    }
}

// ============================================================================
// HMMA attention (R16-exact): Q staged in slot KV1 (one startup barrier),
// windowed bias row (2205 floats), cp.async double-buffered K/V with full
// wait_group 0 per k-block (race-free). 256 threads, 8 warps x 16 q rows.
// ============================================================================
#define BROW_N  2205    // 35*63
#define SM_KV0  8832    // 16B aligned, after 8820B brow
#define SM_KV1  49792
#define KV_KHI  0
#define KV_KLO  10240
#define KV_VHI  20480
#define KV_VLO  30720
#define ATTN_SMEM 90752

__global__ __launch_bounds__(256, 2) void attn_kernel(
    const float* __restrict__ bias_table)
{
    extern __shared__ char smem[];
    float* brow = (float*)(smem);
    const uint32_t sb = smem_u32(smem);

    const int tid = threadIdx.x;
    const int w   = tid >> 5;
    const int l   = tid & 31;

    const int qt = blockIdx.x;
    const int h  = blockIdx.y;
    const int bb = blockIdx.z;

    // windowed bias row: entries idx in [252*qt, 252*qt + 2205)
    {
        const float* bsrc = bias_table + h * NUM_REL_ + qt * 252;
        for (int i = tid; i < BROW_N; i += 256)
            brow[i] = bsrc[i] * 1.4426950408889634f;
    }

    const size_t headbase = (size_t)((bb * H_ + h) * N_) * DK_;

    // ---- stage Q tile into slot KV1 (plain stores) ----
    {
        const uint4* qhi4 = (const uint4*)(g_qhi + headbase + (size_t)qt * 128 * DK_);
        const uint4* qlo4 = (const uint4*)(g_qlo + headbase + (size_t)qt * 128 * DK_);
        #pragma unroll
        for (int i = 0; i < 2; i++) {
            int idx = tid + i * 256;
            int off = (idx >> 2) * RSTRIDE + (idx & 3) * 16;
            *(uint4*)(smem + SM_KV1 + KV_KHI + off) = qhi4[idx];
            *(uint4*)(smem + SM_KV1 + KV_KLO + off) = qlo4[idx];
        }
    }
    __syncthreads();   // Q staged (also covers brow)

    const __nv_bfloat16* khi = g_khi + headbase;
    const __nv_bfloat16* klo = g_klo + headbase;
    const __nv_bfloat16* vhi = g_vhi + headbase;
    const __nv_bfloat16* vlo = g_vlo + headbase;

    auto stage_kv = [&](int kb, uint32_t dst) {
        #pragma unroll
        for (int i = 0; i < 2; i++) {
            int idx = tid + i * 256;
            uint32_t off = (idx >> 2) * RSTRIDE + (idx & 3) * 16;
            size_t ge = (size_t)(kb * 512 + idx) * 8;
            CP16(dst + KV_KHI + off, (const void*)(khi + ge));
            CP16(dst + KV_KLO + off, (const void*)(klo + ge));
            CP16(dst + KV_VHI + off, (const void*)(vhi + ge));
            CP16(dst + KV_VLO + off, (const void*)(vlo + ge));
        }
        CP_COMMIT();
    };

    // kb=0 staging into KV0 can start immediately (Q lives in KV1)
    stage_kv(0, sb + SM_KV0);

    // Q fragments from KV1; per-thread ldsm complete before this thread's
    // kb=0 barrier, and stage_kv(1) (the first KV1 overwrite) comes after it.
    uint32_t qh[2][4], ql[2][4];
    {
        int row = w * 16 + ((l >> 3) & 1) * 8 + (l & 7);
        int colb = (l >> 4) * 16;
        #pragma unroll
        for (int ks = 0; ks < 2; ks++) {
            ldsm_x4(qh[ks], sb + SM_KV1 + KV_KHI + row * RSTRIDE + ks * 32 + colb);
            ldsm_x4(ql[ks], sb + SM_KV1 + KV_KLO + row * RSTRIDE + ks * 32 + colb);
        }
    }

    // per-thread bias index constants (window-relative: subtract 252*qt)
    const int qg1 = qt * 128 + w * 16 + (l >> 2);
    const int qg2 = qg1 + 8;
    const int A1 = (qg1 >> 5) * 63 + (qg1 & 31) + 1984 - qt * 252;
    const int A2 = (qg2 >> 5) * 63 + (qg2 & 31) + 1984 - qt * 252;
    const int lc = 2 * (l & 3);

    float o[4][4];
    #pragma unroll
    for (int i = 0; i < 4; i++)
        #pragma unroll
        for (int j = 0; j < 4; j++) o[i][j] = 0.f;
    float ls0 = 0.f, ls1 = 0.f;

    for (int kb = 0; kb < 8; kb++) {
        const uint32_t base = sb + ((kb & 1) ? SM_KV1 : SM_KV0);
        const uint32_t a_khi = base + KV_KHI;
        const uint32_t a_klo = base + KV_KLO;
        const uint32_t a_vhi = base + KV_VHI;
        const uint32_t a_vlo = base + KV_VLO;

        CP_WAIT0();
        __syncthreads();
        if (kb < 7)
            stage_kv(kb + 1, sb + (((kb + 1) & 1) ? SM_KV1 : SM_KV0));

        #pragma unroll
        for (int hf = 0; hf < 2; hf++) {
            uint32_t ph[16], pl[16];

            #pragma unroll
            for (int ntl = 0; ntl < 8; ntl++) {
                const int nt = hf * 8 + ntl;
                uint32_t kaddr = (nt * 8 + (l & 7)) * RSTRIDE + (l >> 3) * 16;
                uint32_t kh[4], kl[4];
                ldsm_x4(kh, a_khi + kaddr);
                ldsm_x4(kl, a_klo + kaddr);

                const int kr  = kb * 4 + (nt >> 2);
                const int kc0 = (nt & 3) * 8 + lc;
                const int Bv  = kr * 63 + kc0;
                float bv0 = brow[A1 - Bv];
                float bv1 = brow[A1 - Bv - 1];
                float bv2 = brow[A2 - Bv];
                float bv3 = brow[A2 - Bv - 1];

                float acc[4]  = {0.f, 0.f, 0.f, 0.f};
                float acc2[4] = {0.f, 0.f, 0.f, 0.f};
                mma16816(acc,  qh[0], kh + 0);
                mma16816(acc2, qh[0], kl + 0);
                mma16816(acc,  qh[1], kh + 2);
                mma16816(acc2, qh[1], kl + 2);
                mma16816(acc2, ql[0], kh + 0);
                mma16816(acc2, ql[1], kh + 2);

                float p0 = ex2f(acc[0] + acc2[0] + bv0);
                float p1 = ex2f(acc[1] + acc2[1] + bv1);
                float p2 = ex2f(acc[2] + acc2[2] + bv2);
                float p3 = ex2f(acc[3] + acc2[3] + bv3);
                ls0 += p0 + p1;
                ls1 += p2 + p3;

                split2(p0, p1, ph[2 * ntl],     pl[2 * ntl]);
                split2(p2, p3, ph[2 * ntl + 1], pl[2 * ntl + 1]);
            }

            #pragma unroll
            for (int i = 0; i < 2; i++) {
                uint32_t vh[4][4], vl[4][4];
                #pragma unroll
                for (int nt = 0; nt < 4; nt++) {
                    uint32_t vaddr = (hf * 64 + i * 32 + (l >> 3) * 8 + (l & 7)) * RSTRIDE
                                   + nt * 16;
                    ldsm_x4t(vh[nt], a_vhi + vaddr);
                    ldsm_x4t(vl[nt], a_vlo + vaddr);
                }
                #pragma unroll
                for (int nt = 0; nt < 4; nt++) {
                    mma16816(o[nt], ph + 8 * i,     vh[nt] + 0);
                    mma16816(o[nt], ph + 8 * i + 4, vh[nt] + 2);
                }
                #pragma unroll
                for (int nt = 0; nt < 4; nt++) {
                    mma16816(o[nt], ph + 8 * i,     vl[nt] + 0);
                    mma16816(o[nt], ph + 8 * i + 4, vl[nt] + 2);
                }
                #pragma unroll
                for (int nt = 0; nt < 4; nt++) {
                    mma16816(o[nt], pl + 8 * i,     vh[nt] + 0);
                    mma16816(o[nt], pl + 8 * i + 4, vh[nt] + 2);
                }
            }
        }
    }

    ls0 += __shfl_xor_sync(0xffffffffu, ls0, 1);
    ls0 += __shfl_xor_sync(0xffffffffu, ls0, 2);
    ls1 += __shfl_xor_sync(0xffffffffu, ls1, 1);
    ls1 += __shfl_xor_sync(0xffffffffu, ls1, 2);
    const float inv0 = 1.f / ls0;
    const float inv1 = 1.f / ls1;

    const int row0 = bb * N_ + qt * 128 + w * 16 + (l >> 2);
    #pragma unroll
    for (int nt = 0; nt < 4; nt++) {
        int col = nt * 8 + lc;
        size_t e0 = (size_t)row0 * D_ + h * DK_ + col;
        size_t e1 = e0 + 8 * D_;
        uint32_t hi, lo;
        split2(o[nt][0] * inv0, o[nt][1] * inv0, hi, lo);
        *(uint32_t*)(g_ahi + e0) = hi;
        *(uint32_t*)(g_alo + e0) = lo;
        split2(o[nt][2] * inv1, o[nt][3] * inv1, hi, lo);
        *(uint32_t*)(g_ahi + e1) = hi;
        *(uint32_t*)(g_alo + e1) = lo;
    }
}

// ============================================================================
// Output projection. grid = (128, 4), 512 threads. 3-stage.
// ============================================================================
__global__ __launch_bounds__(512, 2) void oproj_hmma(
    const float* __restrict__ bo, float* __restrict__ out)
{
    extern __shared__ __align__(16) char smem[];
    const uint32_t sb = smem_u32(smem);

    const int tid = threadIdx.x;
    const int w = tid >> 5, l = tid & 31;
    const int wr = w & 3, wc = w >> 2;

    const int m0 = blockIdx.x * 128;
    const int j0 = blockIdx.y * 64;

    const __nv_bfloat16* Whi = g_whi + 3 * 65536;
    const __nv_bfloat16* Wlo = g_wlo + 3 * 65536;

    float acc[2][2][4];
    #pragma unroll
    for (int mt = 0; mt < 2; mt++)
        #pragma unroll
        for (int nt = 0; nt < 2; nt++)
            #pragma unroll
            for (int i = 0; i < 4; i++) acc[mt][nt][i] = 0.f;

    gemm_mainloop(acc, sb, g_ahi, g_alo, Whi, Wlo, m0, j0, tid, wr, wc, l);

    #pragma unroll
    for (int mt = 0; mt < 2; mt++) {
        int m1 = m0 + wr * 32 + mt * 16 + (l >> 2);
        #pragma unroll
        for (int nt = 0; nt < 2; nt++) {
            int col = j0 + wc * 16 + nt * 8 + 2 * (l & 3);
            float b0 = bo[col], b1 = bo[col + 1];
            *(float2*)(out + (size_t)m1 * 256 + col) =
                make_float2(acc[mt][nt][0] + b0, acc[mt][nt][1] + b1);
            *(float2*)(out + (size_t)(m1 + 8) * 256 + col) =
                make_float2(acc[mt][nt][2] + b0, acc[mt][nt][3] + b1);
        }
    }
}

// ============================================================================
// Launch — inputs: x, Wq, bq, Wk, bk, Wv, bv, Wo, bo, bias_table, rel_index
// ============================================================================
extern "C" void kernel_launch(void* const* d_in, const int* in_sizes, int n_in,
                              void* d_out, int out_size)
{
    const float* x          = (const float*)d_in[0];
    const float* Wq         = (const float*)d_in[1];
    const float* bq         = (const float*)d_in[2];
    const float* Wk         = (const float*)d_in[3];
    const float* bk         = (const float*)d_in[4];
    const float* Wv         = (const float*)d_in[5];
    const float* bv         = (const float*)d_in[6];
    const float* Wo         = (const float*)d_in[7];
    const float* bo         = (const float*)d_in[8];
    const float* bias_table = (const float*)d_in[9];
    float* out = (float*)d_out;

    cudaFuncSetAttribute(attn_kernel, cudaFuncAttributeMaxDynamicSharedMemorySize, ATTN_SMEM);
    cudaFuncSetAttribute(qkv_hmma,  cudaFuncAttributeMaxDynamicSharedMemorySize, GEMM_SMEM);
    cudaFuncSetAttribute(oproj_hmma, cudaFuncAttributeMaxDynamicSharedMemorySize, GEMM_SMEM);

    convert_kernel<<<4352, 256>>>(x, Wq, Wk, Wv, Wo);
    qkv_hmma<<<dim3(128, 12), 512, GEMM_SMEM>>>(bq, bk, bv);
    attn_kernel<<<dim3(8, 8, 16), 256, ATTN_SMEM>>>(bias_table);
    oproj_hmma<<<dim3(128, 4), 512, GEMM_SMEM>>>(bo, out);
}